// round 1
// baseline (speedup 1.0000x reference)
#include <cuda_runtime.h>

#define EMBED  1024
#define HEADS  16
#define HDIM   64
#define NBATCH 2
#define SEQ    2048
#define NROWS  (NBATCH * SEQ)   // 4096

// Scratch: intermediates live in device globals (no allocation allowed).
__device__ float g_q[NROWS * EMBED];
__device__ float g_k[NROWS * EMBED];
__device__ float g_v[NROWS * EMBED];
__device__ float g_ctx[NROWS * EMBED];

// ---------------------------------------------------------------------------
// GEMM (NT): out[r][c] = sum_k X[r][k] * W[c][k] + b[c]
// X: [4096,1024] row-major, W: [1024,1024] row-major (rows are output cols).
// Block tile 64x64, BK=16, 256 threads, 4x4 micro-tile per thread.
// src_sel / dst_sel pick device-global scratch when the pointer is null.
// ---------------------------------------------------------------------------
__global__ __launch_bounds__(256) void gemm_nt_bias_kernel(
    const float* __restrict__ Xext, const float* __restrict__ W,
    const float* __restrict__ bias, float* __restrict__ out_ext, int dst_sel)
{
    __shared__ float As[64][17];
    __shared__ float Bs[64][17];

    const float* X = Xext ? Xext : g_ctx;
    float* out = out_ext;
    if (!out) out = (dst_sel == 0) ? g_q : (dst_sel == 1) ? g_k : g_v;

    const int t  = threadIdx.x;
    const int tx = t & 15;
    const int ty = t >> 4;
    const int c0 = blockIdx.x * 64;
    const int r0 = blockIdx.y * 64;

    const int lrow = t >> 2;        // 0..63
    const int lk4  = (t & 3) * 4;   // 0,4,8,12

    float acc[4][4];
#pragma unroll
    for (int i = 0; i < 4; i++)
#pragma unroll
        for (int j = 0; j < 4; j++) acc[i][j] = 0.f;

    const float* xp = X + (size_t)(r0 + lrow) * EMBED + lk4;
    const float* wp = W + (size_t)(c0 + lrow) * EMBED + lk4;

    for (int k0 = 0; k0 < EMBED; k0 += 16) {
        float4 a = *(const float4*)(xp + k0);
        float4 b = *(const float4*)(wp + k0);
        As[lrow][lk4 + 0] = a.x; As[lrow][lk4 + 1] = a.y;
        As[lrow][lk4 + 2] = a.z; As[lrow][lk4 + 3] = a.w;
        Bs[lrow][lk4 + 0] = b.x; Bs[lrow][lk4 + 1] = b.y;
        Bs[lrow][lk4 + 2] = b.z; Bs[lrow][lk4 + 3] = b.w;
        __syncthreads();

#pragma unroll
        for (int k = 0; k < 16; k++) {
            float ra[4], rb[4];
#pragma unroll
            for (int i = 0; i < 4; i++) ra[i] = As[ty * 4 + i][k];
#pragma unroll
            for (int j = 0; j < 4; j++) rb[j] = Bs[tx * 4 + j][k];
#pragma unroll
            for (int i = 0; i < 4; i++)
#pragma unroll
                for (int j = 0; j < 4; j++)
                    acc[i][j] = fmaf(ra[i], rb[j], acc[i][j]);
        }
        __syncthreads();
    }

    float4 bb = *(const float4*)(bias + c0 + tx * 4);
#pragma unroll
    for (int i = 0; i < 4; i++) {
        float4 o;
        o.x = acc[i][0] + bb.x;
        o.y = acc[i][1] + bb.y;
        o.z = acc[i][2] + bb.z;
        o.w = acc[i][3] + bb.w;
        *(float4*)(out + (size_t)(r0 + ty * 4 + i) * EMBED + c0 + tx * 4) = o;
    }
}

// ---------------------------------------------------------------------------
// Flash attention: per (n, h, q-tile of 64 rows).
// 64x64 S-tiles, online softmax, P reuses the K smem buffer.
// Q is pre-scaled by 1/sqrt(HDIM) = 0.125 at load.
// ---------------------------------------------------------------------------
#define QPAD 64
#define KPAD 65
#define VPAD 66
#define FLASH_SMEM ((64 * QPAD + 64 * KPAD + 64 * VPAD) * 4)   // 49920 B

__global__ __launch_bounds__(256) void flash_kernel()
{
    extern __shared__ float sm[];
    float* Qs = sm;                       // [64][QPAD]
    float* Ks = sm + 64 * QPAD;           // [64][KPAD] (reused for P)
    float* Vs = sm + 64 * (QPAD + KPAD);  // [64][VPAD]

    const int n  = blockIdx.z;
    const int h  = blockIdx.y;
    const int q0 = blockIdx.x * 64;
    const int t  = threadIdx.x;
    const int tx = t & 15;
    const int ty = t >> 4;

    const float* Qg = g_q + (size_t)n * SEQ * EMBED + h * HDIM;
    const float* Kg = g_k + (size_t)n * SEQ * EMBED + h * HDIM;
    const float* Vg = g_v + (size_t)n * SEQ * EMBED + h * HDIM;

    // Load Q tile (64x64): 1024 float4, 4 per thread, coalesced.
#pragma unroll
    for (int it = 0; it < 4; it++) {
        int fi = t + it * 256;
        int r  = fi >> 4;
        int c  = (fi & 15) * 4;
        float4 v4 = *(const float4*)(Qg + (size_t)(q0 + r) * EMBED + c);
        Qs[r * QPAD + c + 0] = v4.x * 0.125f;
        Qs[r * QPAD + c + 1] = v4.y * 0.125f;
        Qs[r * QPAD + c + 2] = v4.z * 0.125f;
        Qs[r * QPAD + c + 3] = v4.w * 0.125f;
    }

    float m_i[4], l_i[4], oa[4][4];
#pragma unroll
    for (int i = 0; i < 4; i++) {
        m_i[i] = -1e30f;
        l_i[i] = 0.f;
#pragma unroll
        for (int j = 0; j < 4; j++) oa[i][j] = 0.f;
    }

    for (int s0 = 0; s0 < SEQ; s0 += 64) {
        // Load K and V tiles.
#pragma unroll
        for (int it = 0; it < 4; it++) {
            int fi = t + it * 256;
            int r  = fi >> 4;
            int c  = (fi & 15) * 4;
            float4 kv = *(const float4*)(Kg + (size_t)(s0 + r) * EMBED + c);
            float4 vv = *(const float4*)(Vg + (size_t)(s0 + r) * EMBED + c);
            Ks[r * KPAD + c + 0] = kv.x; Ks[r * KPAD + c + 1] = kv.y;
            Ks[r * KPAD + c + 2] = kv.z; Ks[r * KPAD + c + 3] = kv.w;
            Vs[r * VPAD + c + 0] = vv.x; Vs[r * VPAD + c + 1] = vv.y;
            Vs[r * VPAD + c + 2] = vv.z; Vs[r * VPAD + c + 3] = vv.w;
        }
        __syncthreads();

        // S = (Q * 0.125) @ K^T  (64x64, 4x4 per thread)
        float sa[4][4];
#pragma unroll
        for (int i = 0; i < 4; i++)
#pragma unroll
            for (int j = 0; j < 4; j++) sa[i][j] = 0.f;

#pragma unroll 8
        for (int d = 0; d < HDIM; d++) {
            float ra[4], rb[4];
#pragma unroll
            for (int i = 0; i < 4; i++) ra[i] = Qs[(ty * 4 + i) * QPAD + d];
#pragma unroll
            for (int j = 0; j < 4; j++) rb[j] = Ks[(tx * 4 + j) * KPAD + d];
#pragma unroll
            for (int i = 0; i < 4; i++)
#pragma unroll
                for (int j = 0; j < 4; j++)
                    sa[i][j] = fmaf(ra[i], rb[j], sa[i][j]);
        }

        // Online softmax. Row i is owned by the 16 lanes sharing ty;
        // xor-shuffles with offset <16 stay inside that lane group.
#pragma unroll
        for (int i = 0; i < 4; i++) {
            float mx = fmaxf(fmaxf(sa[i][0], sa[i][1]), fmaxf(sa[i][2], sa[i][3]));
#pragma unroll
            for (int o = 8; o > 0; o >>= 1)
                mx = fmaxf(mx, __shfl_xor_sync(0xffffffffu, mx, o));
            float mn   = fmaxf(m_i[i], mx);
            float corr = __expf(m_i[i] - mn);
            m_i[i] = mn;
            float rs = 0.f;
#pragma unroll
            for (int j = 0; j < 4; j++) {
                float p = __expf(sa[i][j] - mn);
                sa[i][j] = p;
                rs += p;
            }
#pragma unroll
            for (int o = 8; o > 0; o >>= 1)
                rs += __shfl_xor_sync(0xffffffffu, rs, o);
            l_i[i] = l_i[i] * corr + rs;
#pragma unroll
            for (int j = 0; j < 4; j++) oa[i][j] *= corr;
        }

        __syncthreads();   // all lanes done reading Ks
        // Write P into the K buffer.
#pragma unroll
        for (int i = 0; i < 4; i++)
#pragma unroll
            for (int j = 0; j < 4; j++)
                Ks[(ty * 4 + i) * KPAD + tx * 4 + j] = sa[i][j];
        __syncthreads();

        // O += P @ V
#pragma unroll 8
        for (int d = 0; d < 64; d++) {
            float rp[4], rv[4];
#pragma unroll
            for (int i = 0; i < 4; i++) rp[i] = Ks[(ty * 4 + i) * KPAD + d];
#pragma unroll
            for (int j = 0; j < 4; j++) rv[j] = Vs[d * VPAD + tx * 4 + j];
#pragma unroll
            for (int i = 0; i < 4; i++)
#pragma unroll
                for (int j = 0; j < 4; j++)
                    oa[i][j] = fmaf(rp[i], rv[j], oa[i][j]);
        }
        __syncthreads();   // before next tile overwrites Ks/Vs
    }

    float* Og = g_ctx + (size_t)n * SEQ * EMBED + h * HDIM;
#pragma unroll
    for (int i = 0; i < 4; i++) {
        float inv = 1.0f / l_i[i];
        float4 o;
        o.x = oa[i][0] * inv;
        o.y = oa[i][1] * inv;
        o.z = oa[i][2] * inv;
        o.w = oa[i][3] * inv;
        *(float4*)(Og + (size_t)(q0 + ty * 4 + i) * EMBED + tx * 4) = o;
    }
}

// ---------------------------------------------------------------------------
// Launch: Q/K/V projections -> flash attention -> output projection.
// ---------------------------------------------------------------------------
extern "C" void kernel_launch(void* const* d_in, const int* in_sizes, int n_in,
                              void* d_out, int out_size)
{
    const float* values  = (const float*)d_in[0];
    const float* keys    = (const float*)d_in[1];
    const float* queries = (const float*)d_in[2];
    const float* W_v = (const float*)d_in[3];
    const float* b_v = (const float*)d_in[4];
    const float* W_k = (const float*)d_in[5];
    const float* b_k = (const float*)d_in[6];
    const float* W_q = (const float*)d_in[7];
    const float* b_q = (const float*)d_in[8];
    const float* W_o = (const float*)d_in[9];
    const float* b_o = (const float*)d_in[10];
    float* out = (float*)d_out;

    // Not a stream op; safe under graph capture. Idempotent.
    cudaFuncSetAttribute(flash_kernel,
                         cudaFuncAttributeMaxDynamicSharedMemorySize, FLASH_SMEM);

    dim3 gblk(256);
    dim3 ggrid(EMBED / 64, NROWS / 64);

    gemm_nt_bias_kernel<<<ggrid, gblk>>>(queries, W_q, b_q, nullptr, 0);
    gemm_nt_bias_kernel<<<ggrid, gblk>>>(keys,    W_k, b_k, nullptr, 1);
    gemm_nt_bias_kernel<<<ggrid, gblk>>>(values,  W_v, b_v, nullptr, 2);

    dim3 fgrid(SEQ / 64, HEADS, NBATCH);
    flash_kernel<<<fgrid, 256, FLASH_SMEM>>>();

    // X = nullptr -> read g_ctx; out = d_out.
    gemm_nt_bias_kernel<<<ggrid, gblk>>>(nullptr, W_o, b_o, out, -1);
}

// round 2
// speedup vs baseline: 1.5354x; 1.5354x over previous
#include <cuda_runtime.h>
#include <cstdint>

#define EMBED  1024
#define HEADS  16
#define HDIM   64
#define NBATCH 2
#define SEQ    2048
#define NROWS  (NBATCH * SEQ)   // 4096

// Scratch: intermediates live in device globals (no allocation allowed).
__device__ float g_q[NROWS * EMBED];
__device__ float g_k[NROWS * EMBED];
__device__ float g_v[NROWS * EMBED];
__device__ float g_ctx[NROWS * EMBED];

// ---------------------------------------------------------------------------
// tf32 tensor-core GEMM (NT): out[r][c] = sum_k X[r][k]*W[c][k] + b[c]
// Block tile 128x128, BK=16, 256 threads (8 warps as 4m x 2n).
// Warp tile 32x64 -> 2 m16 x 8 n8 mma.m16n8k8 fragments.
// cp.async double buffering; XOR-swizzled smem (conflict-free frag loads).
// ---------------------------------------------------------------------------

__device__ __forceinline__ uint32_t f2tf32(float x) {
    uint32_t r;
    asm("cvt.rna.tf32.f32 %0, %1;" : "=r"(r) : "f"(x));
    return r;
}

// swizzled float index inside a [128][16] tile
__device__ __forceinline__ int swz(int row, int k) {
    return row * 16 + ((((k >> 2) ^ ((row >> 1) & 3)) << 2) | (k & 3));
}

#define CP_ASYNC16(dst_u32, src_ptr) \
    asm volatile("cp.async.cg.shared.global [%0], [%1], 16;" :: "r"(dst_u32), "l"(src_ptr))

__global__ __launch_bounds__(256) void gemm_tf32_kernel(
    const float* __restrict__ Xext, const float* __restrict__ W,
    const float* __restrict__ bias, float* __restrict__ out_ext, int dst_sel)
{
    __shared__ float sA[2][128 * 16];
    __shared__ float sB[2][128 * 16];

    const float* X = Xext ? Xext : g_ctx;
    float* out = out_ext;
    if (!out) out = (dst_sel == 0) ? g_q : (dst_sel == 1) ? g_k : g_v;

    const int t    = threadIdx.x;
    const int lane = t & 31;
    const int wid  = t >> 5;
    const int wm   = (wid & 3) * 32;   // warp m offset in block tile
    const int wn   = (wid >> 2) * 64;  // warp n offset
    const int g    = lane >> 2;        // group id 0..7
    const int tig  = lane & 3;         // thread-in-group

    const int c0 = blockIdx.x * 128;   // output-column (W row) base
    const int r0 = blockIdx.y * 128;   // row base

    // per-thread cp.async assignments: 2 chunks of A + 2 of B per BK tile
    const int ldrow0 = t >> 1;                 // rows for idx 0..255 -> 0..127
    const int ldc0   = (t & 1) * 2;            // chunks {0,1} or {2,3}

    uint32_t sA_u32 = (uint32_t)__cvta_generic_to_shared(&sA[0][0]);
    uint32_t sB_u32 = (uint32_t)__cvta_generic_to_shared(&sB[0][0]);

    float acc[2][8][4];
#pragma unroll
    for (int mi = 0; mi < 2; mi++)
#pragma unroll
        for (int ni = 0; ni < 8; ni++)
#pragma unroll
            for (int e = 0; e < 4; e++) acc[mi][ni][e] = 0.f;

    auto issue_tile = [&](int buf, int k0) {
#pragma unroll
        for (int i = 0; i < 2; i++) {
            int row = ldrow0;
            int c   = ldc0 + i;
            int doff = (row * 16 + ((c ^ ((row >> 1) & 3)) << 2)) * 4;  // bytes
            const float* srcA = X + (size_t)(r0 + row) * EMBED + k0 + c * 4;
            const float* srcB = W + (size_t)(c0 + row) * EMBED + k0 + c * 4;
            CP_ASYNC16(sA_u32 + buf * (128 * 16 * 4) + doff, srcA);
            CP_ASYNC16(sB_u32 + buf * (128 * 16 * 4) + doff, srcB);
        }
    };

    issue_tile(0, 0);
    asm volatile("cp.async.commit_group;");

    const int NTILES = EMBED / 16;  // 64
    for (int it = 0; it < NTILES; it++) {
        if (it + 1 < NTILES) {
            issue_tile((it + 1) & 1, (it + 1) * 16);
            asm volatile("cp.async.commit_group;");
            asm volatile("cp.async.wait_group 1;");
        } else {
            asm volatile("cp.async.wait_group 0;");
        }
        __syncthreads();

        const float* A = sA[it & 1];
        const float* B = sB[it & 1];

#pragma unroll
        for (int ks = 0; ks < 2; ks++) {
            const int k0s = ks * 8;
            uint32_t af[2][4];
#pragma unroll
            for (int mi = 0; mi < 2; mi++) {
                int r = wm + mi * 16 + g;
                af[mi][0] = f2tf32(A[swz(r,     k0s + tig)]);
                af[mi][1] = f2tf32(A[swz(r + 8, k0s + tig)]);
                af[mi][2] = f2tf32(A[swz(r,     k0s + tig + 4)]);
                af[mi][3] = f2tf32(A[swz(r + 8, k0s + tig + 4)]);
            }
            uint32_t bf[8][2];
#pragma unroll
            for (int ni = 0; ni < 8; ni++) {
                int n = wn + ni * 8 + g;
                bf[ni][0] = f2tf32(B[swz(n, k0s + tig)]);
                bf[ni][1] = f2tf32(B[swz(n, k0s + tig + 4)]);
            }
#pragma unroll
            for (int mi = 0; mi < 2; mi++)
#pragma unroll
                for (int ni = 0; ni < 8; ni++) {
                    asm volatile(
                        "mma.sync.aligned.m16n8k8.row.col.f32.tf32.tf32.f32 "
                        "{%0,%1,%2,%3}, {%4,%5,%6,%7}, {%8,%9}, {%0,%1,%2,%3};"
                        : "+f"(acc[mi][ni][0]), "+f"(acc[mi][ni][1]),
                          "+f"(acc[mi][ni][2]), "+f"(acc[mi][ni][3])
                        : "r"(af[mi][0]), "r"(af[mi][1]),
                          "r"(af[mi][2]), "r"(af[mi][3]),
                          "r"(bf[ni][0]), "r"(bf[ni][1]));
                }
        }
        __syncthreads();
    }

    // Epilogue: add bias, write fp32.
#pragma unroll
    for (int mi = 0; mi < 2; mi++) {
        int r = r0 + wm + mi * 16 + g;
#pragma unroll
        for (int ni = 0; ni < 8; ni++) {
            int cc = c0 + wn + ni * 8 + 2 * tig;
            float bx = bias[cc], by = bias[cc + 1];
            float2 v0 = make_float2(acc[mi][ni][0] + bx, acc[mi][ni][1] + by);
            float2 v1 = make_float2(acc[mi][ni][2] + bx, acc[mi][ni][3] + by);
            *(float2*)(out + (size_t)r * EMBED + cc)       = v0;
            *(float2*)(out + (size_t)(r + 8) * EMBED + cc) = v1;
        }
    }
}

// ---------------------------------------------------------------------------
// Flash attention: per (n, h, q-tile of 64 rows). (unchanged from R1)
// ---------------------------------------------------------------------------
#define QPAD 64
#define KPAD 65
#define VPAD 66
#define FLASH_SMEM ((64 * QPAD + 64 * KPAD + 64 * VPAD) * 4)   // 49920 B

__global__ __launch_bounds__(256) void flash_kernel()
{
    extern __shared__ float sm[];
    float* Qs = sm;                       // [64][QPAD]
    float* Ks = sm + 64 * QPAD;           // [64][KPAD] (reused for P)
    float* Vs = sm + 64 * (QPAD + KPAD);  // [64][VPAD]

    const int n  = blockIdx.z;
    const int h  = blockIdx.y;
    const int q0 = blockIdx.x * 64;
    const int t  = threadIdx.x;
    const int tx = t & 15;
    const int ty = t >> 4;

    const float* Qg = g_q + (size_t)n * SEQ * EMBED + h * HDIM;
    const float* Kg = g_k + (size_t)n * SEQ * EMBED + h * HDIM;
    const float* Vg = g_v + (size_t)n * SEQ * EMBED + h * HDIM;

#pragma unroll
    for (int it = 0; it < 4; it++) {
        int fi = t + it * 256;
        int r  = fi >> 4;
        int c  = (fi & 15) * 4;
        float4 v4 = *(const float4*)(Qg + (size_t)(q0 + r) * EMBED + c);
        Qs[r * QPAD + c + 0] = v4.x * 0.125f;
        Qs[r * QPAD + c + 1] = v4.y * 0.125f;
        Qs[r * QPAD + c + 2] = v4.z * 0.125f;
        Qs[r * QPAD + c + 3] = v4.w * 0.125f;
    }

    float m_i[4], l_i[4], oa[4][4];
#pragma unroll
    for (int i = 0; i < 4; i++) {
        m_i[i] = -1e30f;
        l_i[i] = 0.f;
#pragma unroll
        for (int j = 0; j < 4; j++) oa[i][j] = 0.f;
    }

    for (int s0 = 0; s0 < SEQ; s0 += 64) {
#pragma unroll
        for (int it = 0; it < 4; it++) {
            int fi = t + it * 256;
            int r  = fi >> 4;
            int c  = (fi & 15) * 4;
            float4 kv = *(const float4*)(Kg + (size_t)(s0 + r) * EMBED + c);
            float4 vv = *(const float4*)(Vg + (size_t)(s0 + r) * EMBED + c);
            Ks[r * KPAD + c + 0] = kv.x; Ks[r * KPAD + c + 1] = kv.y;
            Ks[r * KPAD + c + 2] = kv.z; Ks[r * KPAD + c + 3] = kv.w;
            Vs[r * VPAD + c + 0] = vv.x; Vs[r * VPAD + c + 1] = vv.y;
            Vs[r * VPAD + c + 2] = vv.z; Vs[r * VPAD + c + 3] = vv.w;
        }
        __syncthreads();

        float sa[4][4];
#pragma unroll
        for (int i = 0; i < 4; i++)
#pragma unroll
            for (int j = 0; j < 4; j++) sa[i][j] = 0.f;

#pragma unroll 8
        for (int d = 0; d < HDIM; d++) {
            float ra[4], rb[4];
#pragma unroll
            for (int i = 0; i < 4; i++) ra[i] = Qs[(ty * 4 + i) * QPAD + d];
#pragma unroll
            for (int j = 0; j < 4; j++) rb[j] = Ks[(tx * 4 + j) * KPAD + d];
#pragma unroll
            for (int i = 0; i < 4; i++)
#pragma unroll
                for (int j = 0; j < 4; j++)
                    sa[i][j] = fmaf(ra[i], rb[j], sa[i][j]);
        }

#pragma unroll
        for (int i = 0; i < 4; i++) {
            float mx = fmaxf(fmaxf(sa[i][0], sa[i][1]), fmaxf(sa[i][2], sa[i][3]));
#pragma unroll
            for (int o = 8; o > 0; o >>= 1)
                mx = fmaxf(mx, __shfl_xor_sync(0xffffffffu, mx, o));
            float mn   = fmaxf(m_i[i], mx);
            float corr = __expf(m_i[i] - mn);
            m_i[i] = mn;
            float rs = 0.f;
#pragma unroll
            for (int j = 0; j < 4; j++) {
                float p = __expf(sa[i][j] - mn);
                sa[i][j] = p;
                rs += p;
            }
#pragma unroll
            for (int o = 8; o > 0; o >>= 1)
                rs += __shfl_xor_sync(0xffffffffu, rs, o);
            l_i[i] = l_i[i] * corr + rs;
#pragma unroll
            for (int j = 0; j < 4; j++) oa[i][j] *= corr;
        }

        __syncthreads();
#pragma unroll
        for (int i = 0; i < 4; i++)
#pragma unroll
            for (int j = 0; j < 4; j++)
                Ks[(ty * 4 + i) * KPAD + tx * 4 + j] = sa[i][j];
        __syncthreads();

#pragma unroll 8
        for (int d = 0; d < 64; d++) {
            float rp[4], rv[4];
#pragma unroll
            for (int i = 0; i < 4; i++) rp[i] = Ks[(ty * 4 + i) * KPAD + d];
#pragma unroll
            for (int j = 0; j < 4; j++) rv[j] = Vs[d * VPAD + tx * 4 + j];
#pragma unroll
            for (int i = 0; i < 4; i++)
#pragma unroll
                for (int j = 0; j < 4; j++)
                    oa[i][j] = fmaf(rp[i], rv[j], oa[i][j]);
        }
        __syncthreads();
    }

    float* Og = g_ctx + (size_t)n * SEQ * EMBED + h * HDIM;
#pragma unroll
    for (int i = 0; i < 4; i++) {
        float inv = 1.0f / l_i[i];
        float4 o;
        o.x = oa[i][0] * inv;
        o.y = oa[i][1] * inv;
        o.z = oa[i][2] * inv;
        o.w = oa[i][3] * inv;
        *(float4*)(Og + (size_t)(q0 + ty * 4 + i) * EMBED + tx * 4) = o;
    }
}

// ---------------------------------------------------------------------------
// Launch: Q/K/V projections -> flash attention -> output projection.
// ---------------------------------------------------------------------------
extern "C" void kernel_launch(void* const* d_in, const int* in_sizes, int n_in,
                              void* d_out, int out_size)
{
    const float* values  = (const float*)d_in[0];
    const float* keys    = (const float*)d_in[1];
    const float* queries = (const float*)d_in[2];
    const float* W_v = (const float*)d_in[3];
    const float* b_v = (const float*)d_in[4];
    const float* W_k = (const float*)d_in[5];
    const float* b_k = (const float*)d_in[6];
    const float* W_q = (const float*)d_in[7];
    const float* b_q = (const float*)d_in[8];
    const float* W_o = (const float*)d_in[9];
    const float* b_o = (const float*)d_in[10];
    float* out = (float*)d_out;

    cudaFuncSetAttribute(flash_kernel,
                         cudaFuncAttributeMaxDynamicSharedMemorySize, FLASH_SMEM);

    dim3 gblk(256);
    dim3 ggrid(EMBED / 128, NROWS / 128);   // (8, 32)

    gemm_tf32_kernel<<<ggrid, gblk>>>(queries, W_q, b_q, nullptr, 0);
    gemm_tf32_kernel<<<ggrid, gblk>>>(keys,    W_k, b_k, nullptr, 1);
    gemm_tf32_kernel<<<ggrid, gblk>>>(values,  W_v, b_v, nullptr, 2);

    dim3 fgrid(SEQ / 64, HEADS, NBATCH);
    flash_kernel<<<fgrid, 256, FLASH_SMEM>>>();

    gemm_tf32_kernel<<<ggrid, gblk>>>(nullptr, W_o, b_o, out, -1);
}

// round 3
// speedup vs baseline: 3.2312x; 2.1044x over previous
#include <cuda_runtime.h>
#include <cuda_fp16.h>
#include <cstdint>

#define EMBED  1024
#define HEADS  16
#define HDIM   64
#define NBATCH 2
#define SEQ    2048
#define NROWS  (NBATCH * SEQ)   // 4096

// Scratch (no allocation allowed).
__device__ float  g_q[NROWS * EMBED];
__device__ float  g_k[NROWS * EMBED];
__device__ float  g_v[NROWS * EMBED];
__device__ float  g_ctx[NROWS * EMBED];
__device__ __half g_khi[NROWS * EMBED];
__device__ __half g_klo[NROWS * EMBED];
__device__ __half g_vthi[NBATCH * HEADS * HDIM * SEQ];
__device__ __half g_vtlo[NBATCH * HEADS * HDIM * SEQ];

// ---------------------------------------------------------------------------
// tf32 tensor-core GEMM (NT) — unchanged from R2.
// ---------------------------------------------------------------------------
__device__ __forceinline__ uint32_t f2tf32(float x) {
    uint32_t r;
    asm("cvt.rna.tf32.f32 %0, %1;" : "=r"(r) : "f"(x));
    return r;
}
__device__ __forceinline__ int swz(int row, int k) {
    return row * 16 + ((((k >> 2) ^ ((row >> 1) & 3)) << 2) | (k & 3));
}
#define CP_ASYNC16(dst_u32, src_ptr) \
    asm volatile("cp.async.cg.shared.global [%0], [%1], 16;" :: "r"(dst_u32), "l"(src_ptr))

__global__ __launch_bounds__(256) void gemm_tf32_kernel(
    const float* __restrict__ Xext, const float* __restrict__ W,
    const float* __restrict__ bias, float* __restrict__ out_ext, int dst_sel)
{
    __shared__ float sA[2][128 * 16];
    __shared__ float sB[2][128 * 16];

    const float* X = Xext ? Xext : g_ctx;
    float* out = out_ext;
    if (!out) out = (dst_sel == 0) ? g_q : (dst_sel == 1) ? g_k : g_v;

    const int t    = threadIdx.x;
    const int lane = t & 31;
    const int wid  = t >> 5;
    const int wm   = (wid & 3) * 32;
    const int wn   = (wid >> 2) * 64;
    const int g    = lane >> 2;
    const int tig  = lane & 3;
    const int c0 = blockIdx.x * 128;
    const int r0 = blockIdx.y * 128;
    const int ldrow0 = t >> 1;
    const int ldc0   = (t & 1) * 2;

    uint32_t sA_u32 = (uint32_t)__cvta_generic_to_shared(&sA[0][0]);
    uint32_t sB_u32 = (uint32_t)__cvta_generic_to_shared(&sB[0][0]);

    float acc[2][8][4];
#pragma unroll
    for (int mi = 0; mi < 2; mi++)
#pragma unroll
        for (int ni = 0; ni < 8; ni++)
#pragma unroll
            for (int e = 0; e < 4; e++) acc[mi][ni][e] = 0.f;

    auto issue_tile = [&](int buf, int k0) {
#pragma unroll
        for (int i = 0; i < 2; i++) {
            int row = ldrow0;
            int c   = ldc0 + i;
            int doff = (row * 16 + ((c ^ ((row >> 1) & 3)) << 2)) * 4;
            const float* srcA = X + (size_t)(r0 + row) * EMBED + k0 + c * 4;
            const float* srcB = W + (size_t)(c0 + row) * EMBED + k0 + c * 4;
            CP_ASYNC16(sA_u32 + buf * (128 * 16 * 4) + doff, srcA);
            CP_ASYNC16(sB_u32 + buf * (128 * 16 * 4) + doff, srcB);
        }
    };

    issue_tile(0, 0);
    asm volatile("cp.async.commit_group;");

    const int NTILES = EMBED / 16;
    for (int it = 0; it < NTILES; it++) {
        if (it + 1 < NTILES) {
            issue_tile((it + 1) & 1, (it + 1) * 16);
            asm volatile("cp.async.commit_group;");
            asm volatile("cp.async.wait_group 1;");
        } else {
            asm volatile("cp.async.wait_group 0;");
        }
        __syncthreads();

        const float* A = sA[it & 1];
        const float* B = sB[it & 1];

#pragma unroll
        for (int ks = 0; ks < 2; ks++) {
            const int k0s = ks * 8;
            uint32_t af[2][4];
#pragma unroll
            for (int mi = 0; mi < 2; mi++) {
                int r = wm + mi * 16 + g;
                af[mi][0] = f2tf32(A[swz(r,     k0s + tig)]);
                af[mi][1] = f2tf32(A[swz(r + 8, k0s + tig)]);
                af[mi][2] = f2tf32(A[swz(r,     k0s + tig + 4)]);
                af[mi][3] = f2tf32(A[swz(r + 8, k0s + tig + 4)]);
            }
            uint32_t bf[8][2];
#pragma unroll
            for (int ni = 0; ni < 8; ni++) {
                int n = wn + ni * 8 + g;
                bf[ni][0] = f2tf32(B[swz(n, k0s + tig)]);
                bf[ni][1] = f2tf32(B[swz(n, k0s + tig + 4)]);
            }
#pragma unroll
            for (int mi = 0; mi < 2; mi++)
#pragma unroll
                for (int ni = 0; ni < 8; ni++) {
                    asm volatile(
                        "mma.sync.aligned.m16n8k8.row.col.f32.tf32.tf32.f32 "
                        "{%0,%1,%2,%3}, {%4,%5,%6,%7}, {%8,%9}, {%0,%1,%2,%3};"
                        : "+f"(acc[mi][ni][0]), "+f"(acc[mi][ni][1]),
                          "+f"(acc[mi][ni][2]), "+f"(acc[mi][ni][3])
                        : "r"(af[mi][0]), "r"(af[mi][1]),
                          "r"(af[mi][2]), "r"(af[mi][3]),
                          "r"(bf[ni][0]), "r"(bf[ni][1]));
                }
        }
        __syncthreads();
    }

#pragma unroll
    for (int mi = 0; mi < 2; mi++) {
        int r = r0 + wm + mi * 16 + g;
#pragma unroll
        for (int ni = 0; ni < 8; ni++) {
            int cc = c0 + wn + ni * 8 + 2 * tig;
            float bx = bias[cc], by = bias[cc + 1];
            float2 v0 = make_float2(acc[mi][ni][0] + bx, acc[mi][ni][1] + by);
            float2 v1 = make_float2(acc[mi][ni][2] + bx, acc[mi][ni][3] + by);
            *(float2*)(out + (size_t)r * EMBED + cc)       = v0;
            *(float2*)(out + (size_t)(r + 8) * EMBED + cc) = v1;
        }
    }
}

// ---------------------------------------------------------------------------
// Split helpers: fp32 -> fp16 hi + fp16 lo (residual).
// ---------------------------------------------------------------------------
__device__ __forceinline__ void split2(float x, __half& hi, __half& lo) {
    hi = __float2half_rn(x);
    lo = __float2half_rn(x - __half2float(hi));
}
__device__ __forceinline__ uint32_t h2pack(__half a, __half b) {
    __half2 h = __halves2half2(a, b);
    return *(uint32_t*)&h;
}

// K: elementwise split, same layout.
__global__ __launch_bounds__(256) void splitk_kernel() {
    size_t i = ((size_t)blockIdx.x * 256 + threadIdx.x) * 4;
    float4 x = *(const float4*)(g_k + i);
    __half h0, l0, h1, l1, h2, l2, h3, l3;
    split2(x.x, h0, l0); split2(x.y, h1, l1);
    split2(x.z, h2, l2); split2(x.w, h3, l3);
    uint2 hv = make_uint2(h2pack(h0, h1), h2pack(h2, h3));
    uint2 lv = make_uint2(h2pack(l0, l1), h2pack(l2, l3));
    *(uint2*)(g_khi + i) = hv;
    *(uint2*)(g_klo + i) = lv;
}

// V: per-head transpose -> Vt[(n*H+h)*64 + d][seq], split hi/lo.
__global__ __launch_bounds__(256) void splitvt_kernel() {
    __shared__ float tile[64][65];
    const int n = blockIdx.z, h = blockIdx.y, s0 = blockIdx.x * 64;
    const int t = threadIdx.x;
#pragma unroll
    for (int i = 0; i < 4; i++) {
        int fi = t + i * 256;            // 1024 float4
        int r  = fi >> 4;
        int c4 = fi & 15;
        float4 v = *(const float4*)(g_v + ((size_t)n * SEQ + s0 + r) * EMBED + h * HDIM + c4 * 4);
        tile[r][c4 * 4 + 0] = v.x; tile[r][c4 * 4 + 1] = v.y;
        tile[r][c4 * 4 + 2] = v.z; tile[r][c4 * 4 + 3] = v.w;
    }
    __syncthreads();
#pragma unroll
    for (int i = 0; i < 4; i++) {
        int fi = t + i * 256;
        int d   = fi >> 4;
        int sc4 = fi & 15;
        size_t base = ((size_t)(n * HEADS + h) * HDIM + d) * SEQ + s0 + sc4 * 4;
        __half hh[4], ll[4];
#pragma unroll
        for (int j = 0; j < 4; j++) split2(tile[sc4 * 4 + j][d], hh[j], ll[j]);
        *(uint2*)(g_vthi + base) = make_uint2(h2pack(hh[0], hh[1]), h2pack(hh[2], hh[3]));
        *(uint2*)(g_vtlo + base) = make_uint2(h2pack(ll[0], ll[1]), h2pack(ll[2], ll[3]));
    }
}

// ---------------------------------------------------------------------------
// Tensor-core flash attention, fp16-split (3-MMA) for near-fp32 accuracy.
// Grid (SEQ/64, HEADS, NBATCH), 128 threads (4 warps, m16 each).
// ---------------------------------------------------------------------------
#define FT  4096                   // halves per tile array (64x64)
#define FSTAGE (4 * FT)            // Khi,Klo,Vthi,Vtlo
#define FLASH16_SMEM (2 * FSTAGE * 2)   // 65536 B

__device__ __forceinline__ int swzh(int r, int c) {
    return (r << 6) + ((((c >> 3) ^ (r & 7)) << 3) | (c & 7));
}
__device__ __forceinline__ void mma16816(float* c, const uint32_t* a, const uint32_t* b) {
    asm volatile(
        "mma.sync.aligned.m16n8k16.row.col.f32.f16.f16.f32 "
        "{%0,%1,%2,%3}, {%4,%5,%6,%7}, {%8,%9}, {%0,%1,%2,%3};"
        : "+f"(c[0]), "+f"(c[1]), "+f"(c[2]), "+f"(c[3])
        : "r"(a[0]), "r"(a[1]), "r"(a[2]), "r"(a[3]), "r"(b[0]), "r"(b[1]));
}
__device__ __forceinline__ uint32_t packf2(float x, float y) {
    __half2 h = __floats2half2_rn(x, y);
    return *(uint32_t*)&h;
}
__device__ __forceinline__ uint32_t packlo(float x, float y, uint32_t hi) {
    __half2 h = *(__half2*)&hi;
    return packf2(x - __low2float(h), y - __high2float(h));
}

__global__ __launch_bounds__(128) void flash16_kernel() {
    extern __shared__ __half fsm[];
    const int n  = blockIdx.z;
    const int h  = blockIdx.y;
    const int q0 = blockIdx.x * 64;
    const int t    = threadIdx.x;
    const int lane = t & 31;
    const int wid  = t >> 5;
    const int g    = lane >> 2;
    const int tg   = lane & 3;
    const int wm   = wid * 16;

    const uint32_t smem_u32 = (uint32_t)__cvta_generic_to_shared(fsm);

    // ---- Q A-fragments (scaled by 0.125, split hi/lo), 4 k-steps ----
    uint32_t qa_h[4][4], qa_l[4][4];
    {
        const float* Qg = g_q + ((size_t)n * SEQ + q0 + wm) * EMBED + h * HDIM;
#pragma unroll
        for (int s = 0; s < 4; s++) {
            int c0 = 16 * s + 2 * tg;
#pragma unroll
            for (int rr = 0; rr < 2; rr++) {        // regs 0/1: rows g, g+8 (k lo 8)
                int row = g + rr * 8;
                float2 q01 = *(const float2*)(Qg + (size_t)row * EMBED + c0);
                float2 q23 = *(const float2*)(Qg + (size_t)row * EMBED + c0 + 8);
                q01.x *= 0.125f; q01.y *= 0.125f;
                q23.x *= 0.125f; q23.y *= 0.125f;
                qa_h[s][rr]     = packf2(q01.x, q01.y);
                qa_l[s][rr]     = packlo(q01.x, q01.y, qa_h[s][rr]);
                qa_h[s][rr + 2] = packf2(q23.x, q23.y);
                qa_l[s][rr + 2] = packlo(q23.x, q23.y, qa_h[s][rr + 2]);
            }
        }
    }

    float oacc[8][4];
#pragma unroll
    for (int nf = 0; nf < 8; nf++)
#pragma unroll
        for (int e = 0; e < 4; e++) oacc[nf][e] = 0.f;
    float m0 = -1e30f, m1 = -1e30f, l0 = 0.f, l1 = 0.f;

    const __half* srcK_hi = g_khi + ((size_t)n * SEQ) * EMBED + h * HDIM;
    const __half* srcK_lo = g_klo + ((size_t)n * SEQ) * EMBED + h * HDIM;
    const __half* srcV_hi = g_vthi + (size_t)(n * HEADS + h) * HDIM * SEQ;
    const __half* srcV_lo = g_vtlo + (size_t)(n * HEADS + h) * HDIM * SEQ;

    auto issue = [&](int tileidx, int buf) {
        int s0 = tileidx * 64;
#pragma unroll
        for (int i = 0; i < 4; i++) {
            int gid = t + i * 128;          // 512 granules per array
            int r = gid >> 3;               // 0..63
            int c = gid & 7;                // chunk
            uint32_t dsth = (uint32_t)(buf * FSTAGE + r * 64 + ((c ^ (r & 7)) << 3));
            // K hi/lo: row = seq, col = dim
            CP_ASYNC16(smem_u32 + (dsth) * 2,
                       srcK_hi + (size_t)(s0 + r) * EMBED + c * 8);
            CP_ASYNC16(smem_u32 + (dsth + FT) * 2,
                       srcK_lo + (size_t)(s0 + r) * EMBED + c * 8);
            // Vt hi/lo: row = dim, col = seq
            CP_ASYNC16(smem_u32 + (dsth + 2 * FT) * 2,
                       srcV_hi + (size_t)r * SEQ + s0 + c * 8);
            CP_ASYNC16(smem_u32 + (dsth + 3 * FT) * 2,
                       srcV_lo + (size_t)r * SEQ + s0 + c * 8);
        }
        asm volatile("cp.async.commit_group;");
    };

    issue(0, 0);

    const int NT = SEQ / 64;   // 32
    for (int it = 0; it < NT; it++) {
        if (it + 1 < NT) {
            issue(it + 1, (it + 1) & 1);
            asm volatile("cp.async.wait_group 1;");
        } else {
            asm volatile("cp.async.wait_group 0;");
        }
        __syncthreads();

        const __half* Kh = fsm + (it & 1) * FSTAGE;
        const __half* Kl = Kh + FT;
        const __half* Vh = Kh + 2 * FT;
        const __half* Vl = Kh + 3 * FT;

        // ---- S = Q K^T (fp16-split 3-MMA) ----
        float sa[8][4];
#pragma unroll
        for (int nf = 0; nf < 8; nf++)
#pragma unroll
            for (int e = 0; e < 4; e++) sa[nf][e] = 0.f;

#pragma unroll
        for (int s = 0; s < 4; s++) {
            int cc = 16 * s + 2 * tg;
#pragma unroll
            for (int nh = 0; nh < 2; nh++) {
                uint32_t bh[4][2], bl[4][2];
#pragma unroll
                for (int j = 0; j < 4; j++) {
                    int rr = 8 * (4 * nh + j) + g;
                    bh[j][0] = *(const uint32_t*)&Kh[swzh(rr, cc)];
                    bh[j][1] = *(const uint32_t*)&Kh[swzh(rr, cc + 8)];
                    bl[j][0] = *(const uint32_t*)&Kl[swzh(rr, cc)];
                    bl[j][1] = *(const uint32_t*)&Kl[swzh(rr, cc + 8)];
                }
#pragma unroll
                for (int j = 0; j < 4; j++) mma16816(sa[4 * nh + j], qa_h[s], bh[j]);
#pragma unroll
                for (int j = 0; j < 4; j++) mma16816(sa[4 * nh + j], qa_h[s], bl[j]);
#pragma unroll
                for (int j = 0; j < 4; j++) mma16816(sa[4 * nh + j], qa_l[s], bh[j]);
            }
        }

        // ---- online softmax (fp32) ----
        float mx0 = -1e30f, mx1 = -1e30f;
#pragma unroll
        for (int nf = 0; nf < 8; nf++) {
            mx0 = fmaxf(mx0, fmaxf(sa[nf][0], sa[nf][1]));
            mx1 = fmaxf(mx1, fmaxf(sa[nf][2], sa[nf][3]));
        }
        mx0 = fmaxf(mx0, __shfl_xor_sync(0xffffffffu, mx0, 1));
        mx0 = fmaxf(mx0, __shfl_xor_sync(0xffffffffu, mx0, 2));
        mx1 = fmaxf(mx1, __shfl_xor_sync(0xffffffffu, mx1, 1));
        mx1 = fmaxf(mx1, __shfl_xor_sync(0xffffffffu, mx1, 2));
        float mn0 = fmaxf(m0, mx0), mn1 = fmaxf(m1, mx1);
        float corr0 = __expf(m0 - mn0), corr1 = __expf(m1 - mn1);
        m0 = mn0; m1 = mn1;
        float rs0 = 0.f, rs1 = 0.f;
#pragma unroll
        for (int nf = 0; nf < 8; nf++) {
            sa[nf][0] = __expf(sa[nf][0] - mn0); rs0 += sa[nf][0];
            sa[nf][1] = __expf(sa[nf][1] - mn0); rs0 += sa[nf][1];
            sa[nf][2] = __expf(sa[nf][2] - mn1); rs1 += sa[nf][2];
            sa[nf][3] = __expf(sa[nf][3] - mn1); rs1 += sa[nf][3];
        }
        rs0 += __shfl_xor_sync(0xffffffffu, rs0, 1);
        rs0 += __shfl_xor_sync(0xffffffffu, rs0, 2);
        rs1 += __shfl_xor_sync(0xffffffffu, rs1, 1);
        rs1 += __shfl_xor_sync(0xffffffffu, rs1, 2);
        l0 = l0 * corr0 + rs0;
        l1 = l1 * corr1 + rs1;
#pragma unroll
        for (int nf = 0; nf < 8; nf++) {
            oacc[nf][0] *= corr0; oacc[nf][1] *= corr0;
            oacc[nf][2] *= corr1; oacc[nf][3] *= corr1;
        }

        // ---- P fragments (C-layout -> A-layout, split hi/lo) ----
        uint32_t pa_h[4][4], pa_l[4][4];
#pragma unroll
        for (int sp = 0; sp < 4; sp++) {
            pa_h[sp][0] = packf2(sa[2 * sp][0], sa[2 * sp][1]);
            pa_l[sp][0] = packlo(sa[2 * sp][0], sa[2 * sp][1], pa_h[sp][0]);
            pa_h[sp][1] = packf2(sa[2 * sp][2], sa[2 * sp][3]);
            pa_l[sp][1] = packlo(sa[2 * sp][2], sa[2 * sp][3], pa_h[sp][1]);
            pa_h[sp][2] = packf2(sa[2 * sp + 1][0], sa[2 * sp + 1][1]);
            pa_l[sp][2] = packlo(sa[2 * sp + 1][0], sa[2 * sp + 1][1], pa_h[sp][2]);
            pa_h[sp][3] = packf2(sa[2 * sp + 1][2], sa[2 * sp + 1][3]);
            pa_l[sp][3] = packlo(sa[2 * sp + 1][2], sa[2 * sp + 1][3], pa_h[sp][3]);
        }

        // ---- O += P V (fp16-split 3-MMA) ----
#pragma unroll
        for (int sp = 0; sp < 4; sp++) {
            int cc = 16 * sp + 2 * tg;     // seq col
#pragma unroll
            for (int nh = 0; nh < 2; nh++) {
                uint32_t bh[4][2], bl[4][2];
#pragma unroll
                for (int j = 0; j < 4; j++) {
                    int rr = 8 * (4 * nh + j) + g;   // dim row
                    bh[j][0] = *(const uint32_t*)&Vh[swzh(rr, cc)];
                    bh[j][1] = *(const uint32_t*)&Vh[swzh(rr, cc + 8)];
                    bl[j][0] = *(const uint32_t*)&Vl[swzh(rr, cc)];
                    bl[j][1] = *(const uint32_t*)&Vl[swzh(rr, cc + 8)];
                }
#pragma unroll
                for (int j = 0; j < 4; j++) mma16816(oacc[4 * nh + j], pa_h[sp], bh[j]);
#pragma unroll
                for (int j = 0; j < 4; j++) mma16816(oacc[4 * nh + j], pa_h[sp], bl[j]);
#pragma unroll
                for (int j = 0; j < 4; j++) mma16816(oacc[4 * nh + j], pa_l[sp], bh[j]);
            }
        }
        __syncthreads();
    }

    // ---- epilogue ----
    float* Og = g_ctx + ((size_t)n * SEQ + q0 + wm) * EMBED + h * HDIM;
    float inv0 = 1.0f / l0, inv1 = 1.0f / l1;
#pragma unroll
    for (int nf = 0; nf < 8; nf++) {
        int cc = 8 * nf + 2 * tg;
        *(float2*)(Og + (size_t)g * EMBED + cc) =
            make_float2(oacc[nf][0] * inv0, oacc[nf][1] * inv0);
        *(float2*)(Og + (size_t)(g + 8) * EMBED + cc) =
            make_float2(oacc[nf][2] * inv1, oacc[nf][3] * inv1);
    }
}

// ---------------------------------------------------------------------------
// Launch
// ---------------------------------------------------------------------------
extern "C" void kernel_launch(void* const* d_in, const int* in_sizes, int n_in,
                              void* d_out, int out_size)
{
    const float* values  = (const float*)d_in[0];
    const float* keys    = (const float*)d_in[1];
    const float* queries = (const float*)d_in[2];
    const float* W_v = (const float*)d_in[3];
    const float* b_v = (const float*)d_in[4];
    const float* W_k = (const float*)d_in[5];
    const float* b_k = (const float*)d_in[6];
    const float* W_q = (const float*)d_in[7];
    const float* b_q = (const float*)d_in[8];
    const float* W_o = (const float*)d_in[9];
    const float* b_o = (const float*)d_in[10];
    float* out = (float*)d_out;

    cudaFuncSetAttribute(flash16_kernel,
                         cudaFuncAttributeMaxDynamicSharedMemorySize, FLASH16_SMEM);

    dim3 gblk(256);
    dim3 ggrid(EMBED / 128, NROWS / 128);

    gemm_tf32_kernel<<<ggrid, gblk>>>(queries, W_q, b_q, nullptr, 0);
    gemm_tf32_kernel<<<ggrid, gblk>>>(keys,    W_k, b_k, nullptr, 1);
    gemm_tf32_kernel<<<ggrid, gblk>>>(values,  W_v, b_v, nullptr, 2);

    splitk_kernel<<<(NROWS * EMBED) / (256 * 4), 256>>>();
    splitvt_kernel<<<dim3(SEQ / 64, HEADS, NBATCH), 256>>>();

    flash16_kernel<<<dim3(SEQ / 64, HEADS, NBATCH), 128, FLASH16_SMEM>>>();

    gemm_tf32_kernel<<<ggrid, gblk>>>(nullptr, W_o, b_o, out, -1);
}

// round 7
// speedup vs baseline: 3.5974x; 1.1133x over previous
#include <cuda_runtime.h>
#include <cuda_fp16.h>
#include <cstdint>

#define EMBED  1024
#define HEADS  16
#define HDIM   64
#define NBATCH 2
#define SEQ    2048
#define NROWS  (NBATCH * SEQ)   // 4096

// Scratch (no allocation allowed).
__device__ float  g_q[NROWS * EMBED];
__device__ float  g_k[NROWS * EMBED];
__device__ float  g_v[NROWS * EMBED];
__device__ float  g_ctx[NROWS * EMBED];
__device__ __half g_khi[NROWS * EMBED];
__device__ __half g_klo[NROWS * EMBED];
__device__ __half g_vthi[NBATCH * HEADS * HDIM * SEQ];
__device__ __half g_vtlo[NBATCH * HEADS * HDIM * SEQ];
// GEMM operand splits (reused across the 4 GEMMs; stream-serialized).
__device__ __half g_ahi[NROWS * EMBED];
__device__ __half g_alo[NROWS * EMBED];
__device__ __half g_whi[EMBED * EMBED];
__device__ __half g_wlo[EMBED * EMBED];

#define CP_ASYNC16(dst_u32, src_ptr) \
    asm volatile("cp.async.cg.shared.global [%0], [%1], 16;" :: "r"(dst_u32), "l"(src_ptr))

__device__ __forceinline__ void split2(float x, __half& hi, __half& lo) {
    hi = __float2half_rn(x);
    lo = __float2half_rn(x - __half2float(hi));
}
__device__ __forceinline__ uint32_t h2pack(__half a, __half b) {
    __half2 h = __halves2half2(a, b);
    return *(uint32_t*)&h;
}
__device__ __forceinline__ void mma16816(float* c, const uint32_t* a, const uint32_t* b) {
    asm volatile(
        "mma.sync.aligned.m16n8k16.row.col.f32.f16.f16.f32 "
        "{%0,%1,%2,%3}, {%4,%5,%6,%7}, {%8,%9}, {%0,%1,%2,%3};"
        : "+f"(c[0]), "+f"(c[1]), "+f"(c[2]), "+f"(c[3])
        : "r"(a[0]), "r"(a[1]), "r"(a[2]), "r"(a[3]), "r"(b[0]), "r"(b[1]));
}
__device__ __forceinline__ uint32_t packf2(float x, float y) {
    __half2 h = __floats2half2_rn(x, y);
    return *(uint32_t*)&h;
}
__device__ __forceinline__ uint32_t packlo(float x, float y, uint32_t hi) {
    __half2 h = *(__half2*)&hi;
    return packf2(x - __low2float(h), y - __high2float(h));
}

// ---------------------------------------------------------------------------
// fp32 -> fp16 hi/lo split. Device-global destinations selected IN DEVICE CODE
// (passing __device__ symbols from host was the R4-R6 bug).
// src_ext == nullptr -> read g_ctx. dst_sel: 0 -> (g_ahi,g_alo), 1 -> (g_whi,g_wlo).
// ---------------------------------------------------------------------------
__global__ __launch_bounds__(256) void split_kernel(
    const float* __restrict__ src_ext, int dst_sel)
{
    const float* src = src_ext ? src_ext : g_ctx;
    __half* hi = (dst_sel == 0) ? g_ahi : g_whi;
    __half* lo = (dst_sel == 0) ? g_alo : g_wlo;
    size_t i = ((size_t)blockIdx.x * 256 + threadIdx.x) * 4;
    float4 x = *(const float4*)(src + i);
    __half h0, l0, h1, l1, h2, l2, h3, l3;
    split2(x.x, h0, l0); split2(x.y, h1, l1);
    split2(x.z, h2, l2); split2(x.w, h3, l3);
    *(uint2*)(hi + i) = make_uint2(h2pack(h0, h1), h2pack(h2, h3));
    *(uint2*)(lo + i) = make_uint2(h2pack(l0, l1), h2pack(l2, l3));
}

// ---------------------------------------------------------------------------
// fp16-split 3-MMA GEMM (NT): out[r][c] = sum_k X[r][k]*W[c][k] + b[c]
// Operands read from g_ahi/g_alo (X) and g_whi/g_wlo (W) device globals.
// Block 128x128, BK=32, 128 threads (4 warps as 2m x 2n, 64x64 warp tiles).
// smem: 2 logical rows packed per 64-half physical row, XOR-swizzled chunks
// -> every cp.async granule 16B-aligned, fragment loads bank-conflict-free.
// ---------------------------------------------------------------------------
#define GARR   (128 * 32)             // 4096 halves per array
#define GSTAGE (4 * GARR)             // Ahi,Alo,Bhi,Blo
#define GEMM16_SMEM (2 * GSTAGE * 2)  // 65536 bytes

// logical (row in [0,128), kc in [0,32) halves) -> physical half index
__device__ __forceinline__ int gswz(int r, int kc) {
    int sr = r >> 1;
    int c  = ((r & 1) << 5) | kc;
    return sr * 64 + ((((c >> 3) ^ (sr & 7)) << 3) | (c & 7));
}

__global__ __launch_bounds__(128) void gemm16_kernel(
    const float* __restrict__ bias, float* __restrict__ out_ext, int dst_sel)
{
    extern __shared__ __half gsm[];
    const __half* Ahi_g = g_ahi;
    const __half* Alo_g = g_alo;
    const __half* Bhi_g = g_whi;
    const __half* Blo_g = g_wlo;
    float* out = out_ext;
    if (!out) out = (dst_sel == 0) ? g_q : (dst_sel == 1) ? g_k : g_v;

    const int t    = threadIdx.x;
    const int lane = t & 31;
    const int wid  = t >> 5;
    const int g    = lane >> 2;
    const int tg   = lane & 3;
    const int wm   = (wid & 1) * 64;
    const int wn   = (wid >> 1) * 64;
    const int c0 = blockIdx.x * 128;
    const int r0 = blockIdx.y * 128;

    const uint32_t smem_u32 = (uint32_t)__cvta_generic_to_shared(gsm);

    float acc[4][8][4];
#pragma unroll
    for (int mi = 0; mi < 4; mi++)
#pragma unroll
        for (int ni = 0; ni < 8; ni++)
#pragma unroll
            for (int e = 0; e < 4; e++) acc[mi][ni][e] = 0.f;

    auto issue = [&](int buf, int k0) {
#pragma unroll
        for (int i = 0; i < 4; i++) {
            int gid = t + i * 128;          // 512 granules of 16B per array
            int row = gid >> 2;             // 0..127
            int ch  = gid & 3;              // 16B chunk (8 halves)
            uint32_t dst = smem_u32 + (uint32_t)(buf * GSTAGE + gswz(row, ch * 8)) * 2;
            size_t aoff = (size_t)(r0 + row) * EMBED + k0 + ch * 8;
            size_t boff = (size_t)(c0 + row) * EMBED + k0 + ch * 8;
            CP_ASYNC16(dst,                Ahi_g + aoff);
            CP_ASYNC16(dst + GARR * 2,     Alo_g + aoff);
            CP_ASYNC16(dst + 2 * GARR * 2, Bhi_g + boff);
            CP_ASYNC16(dst + 3 * GARR * 2, Blo_g + boff);
        }
        asm volatile("cp.async.commit_group;");
    };

    issue(0, 0);

    const int NT = EMBED / 32;   // 32
    for (int it = 0; it < NT; it++) {
        if (it + 1 < NT) {
            issue((it + 1) & 1, (it + 1) * 32);
            asm volatile("cp.async.wait_group 1;");
        } else {
            asm volatile("cp.async.wait_group 0;");
        }
        __syncthreads();

        const __half* Ah = gsm + (it & 1) * GSTAGE;
        const __half* Al = Ah + GARR;
        const __half* Bh = Ah + 2 * GARR;
        const __half* Bl = Ah + 3 * GARR;

#pragma unroll
        for (int ks = 0; ks < 2; ks++) {
            const int kc = ks * 16 + 2 * tg;
            uint32_t bh[8][2], bl[8][2];
#pragma unroll
            for (int ni = 0; ni < 8; ni++) {
                int rr = wn + ni * 8 + g;
                bh[ni][0] = *(const uint32_t*)&Bh[gswz(rr, kc)];
                bh[ni][1] = *(const uint32_t*)&Bh[gswz(rr, kc + 8)];
                bl[ni][0] = *(const uint32_t*)&Bl[gswz(rr, kc)];
                bl[ni][1] = *(const uint32_t*)&Bl[gswz(rr, kc + 8)];
            }
#pragma unroll
            for (int mi = 0; mi < 4; mi++) {
                int r = wm + mi * 16 + g;
                uint32_t ah[4], al[4];
                ah[0] = *(const uint32_t*)&Ah[gswz(r, kc)];
                ah[1] = *(const uint32_t*)&Ah[gswz(r + 8, kc)];
                ah[2] = *(const uint32_t*)&Ah[gswz(r, kc + 8)];
                ah[3] = *(const uint32_t*)&Ah[gswz(r + 8, kc + 8)];
                al[0] = *(const uint32_t*)&Al[gswz(r, kc)];
                al[1] = *(const uint32_t*)&Al[gswz(r + 8, kc)];
                al[2] = *(const uint32_t*)&Al[gswz(r, kc + 8)];
                al[3] = *(const uint32_t*)&Al[gswz(r + 8, kc + 8)];
#pragma unroll
                for (int ni = 0; ni < 8; ni++) mma16816(acc[mi][ni], ah, bh[ni]);
#pragma unroll
                for (int ni = 0; ni < 8; ni++) mma16816(acc[mi][ni], ah, bl[ni]);
#pragma unroll
                for (int ni = 0; ni < 8; ni++) mma16816(acc[mi][ni], al, bh[ni]);
            }
        }
        __syncthreads();
    }

#pragma unroll
    for (int mi = 0; mi < 4; mi++) {
        int r = r0 + wm + mi * 16 + g;
#pragma unroll
        for (int ni = 0; ni < 8; ni++) {
            int cc = c0 + wn + ni * 8 + 2 * tg;
            float bx = bias[cc], by = bias[cc + 1];
            *(float2*)(out + (size_t)r * EMBED + cc) =
                make_float2(acc[mi][ni][0] + bx, acc[mi][ni][1] + by);
            *(float2*)(out + (size_t)(r + 8) * EMBED + cc) =
                make_float2(acc[mi][ni][2] + bx, acc[mi][ni][3] + by);
        }
    }
}

// ---------------------------------------------------------------------------
// K split + V transpose/split for flash (unchanged; globals referenced in
// device code only).
// ---------------------------------------------------------------------------
__global__ __launch_bounds__(256) void splitk_kernel() {
    size_t i = ((size_t)blockIdx.x * 256 + threadIdx.x) * 4;
    float4 x = *(const float4*)(g_k + i);
    __half h0, l0, h1, l1, h2, l2, h3, l3;
    split2(x.x, h0, l0); split2(x.y, h1, l1);
    split2(x.z, h2, l2); split2(x.w, h3, l3);
    *(uint2*)(g_khi + i) = make_uint2(h2pack(h0, h1), h2pack(h2, h3));
    *(uint2*)(g_klo + i) = make_uint2(h2pack(l0, l1), h2pack(l2, l3));
}

__global__ __launch_bounds__(256) void splitvt_kernel() {
    __shared__ float tile[64][65];
    const int n = blockIdx.z, h = blockIdx.y, s0 = blockIdx.x * 64;
    const int t = threadIdx.x;
#pragma unroll
    for (int i = 0; i < 4; i++) {
        int fi = t + i * 256;
        int r  = fi >> 4;
        int c4 = fi & 15;
        float4 v = *(const float4*)(g_v + ((size_t)n * SEQ + s0 + r) * EMBED + h * HDIM + c4 * 4);
        tile[r][c4 * 4 + 0] = v.x; tile[r][c4 * 4 + 1] = v.y;
        tile[r][c4 * 4 + 2] = v.z; tile[r][c4 * 4 + 3] = v.w;
    }
    __syncthreads();
#pragma unroll
    for (int i = 0; i < 4; i++) {
        int fi = t + i * 256;
        int d   = fi >> 4;
        int sc4 = fi & 15;
        size_t base = ((size_t)(n * HEADS + h) * HDIM + d) * SEQ + s0 + sc4 * 4;
        __half hh[4], ll[4];
#pragma unroll
        for (int j = 0; j < 4; j++) split2(tile[sc4 * 4 + j][d], hh[j], ll[j]);
        *(uint2*)(g_vthi + base) = make_uint2(h2pack(hh[0], hh[1]), h2pack(hh[2], hh[3]));
        *(uint2*)(g_vtlo + base) = make_uint2(h2pack(ll[0], ll[1]), h2pack(ll[2], ll[3]));
    }
}

// ---------------------------------------------------------------------------
// Tensor-core flash attention, fp16-split (3-MMA) — unchanged (proven R3).
// ---------------------------------------------------------------------------
#define FT  4096
#define FSTAGE (4 * FT)
#define FLASH16_SMEM (2 * FSTAGE * 2)   // 65536 B

__device__ __forceinline__ int swzh(int r, int c) {
    return (r << 6) + ((((c >> 3) ^ (r & 7)) << 3) | (c & 7));
}

__global__ __launch_bounds__(128) void flash16_kernel() {
    extern __shared__ __half fsm[];
    const int n  = blockIdx.z;
    const int h  = blockIdx.y;
    const int q0 = blockIdx.x * 64;
    const int t    = threadIdx.x;
    const int lane = t & 31;
    const int wid  = t >> 5;
    const int g    = lane >> 2;
    const int tg   = lane & 3;
    const int wm   = wid * 16;

    const uint32_t smem_u32 = (uint32_t)__cvta_generic_to_shared(fsm);

    uint32_t qa_h[4][4], qa_l[4][4];
    {
        const float* Qg = g_q + ((size_t)n * SEQ + q0 + wm) * EMBED + h * HDIM;
#pragma unroll
        for (int s = 0; s < 4; s++) {
            int c0 = 16 * s + 2 * tg;
#pragma unroll
            for (int rr = 0; rr < 2; rr++) {
                int row = g + rr * 8;
                float2 q01 = *(const float2*)(Qg + (size_t)row * EMBED + c0);
                float2 q23 = *(const float2*)(Qg + (size_t)row * EMBED + c0 + 8);
                q01.x *= 0.125f; q01.y *= 0.125f;
                q23.x *= 0.125f; q23.y *= 0.125f;
                qa_h[s][rr]     = packf2(q01.x, q01.y);
                qa_l[s][rr]     = packlo(q01.x, q01.y, qa_h[s][rr]);
                qa_h[s][rr + 2] = packf2(q23.x, q23.y);
                qa_l[s][rr + 2] = packlo(q23.x, q23.y, qa_h[s][rr + 2]);
            }
        }
    }

    float oacc[8][4];
#pragma unroll
    for (int nf = 0; nf < 8; nf++)
#pragma unroll
        for (int e = 0; e < 4; e++) oacc[nf][e] = 0.f;
    float m0 = -1e30f, m1 = -1e30f, l0 = 0.f, l1 = 0.f;

    const __half* srcK_hi = g_khi + ((size_t)n * SEQ) * EMBED + h * HDIM;
    const __half* srcK_lo = g_klo + ((size_t)n * SEQ) * EMBED + h * HDIM;
    const __half* srcV_hi = g_vthi + (size_t)(n * HEADS + h) * HDIM * SEQ;
    const __half* srcV_lo = g_vtlo + (size_t)(n * HEADS + h) * HDIM * SEQ;

    auto issue = [&](int tileidx, int buf) {
        int s0 = tileidx * 64;
#pragma unroll
        for (int i = 0; i < 4; i++) {
            int gid = t + i * 128;
            int r = gid >> 3;
            int c = gid & 7;
            uint32_t dsth = (uint32_t)(buf * FSTAGE + r * 64 + ((c ^ (r & 7)) << 3));
            CP_ASYNC16(smem_u32 + (dsth) * 2,
                       srcK_hi + (size_t)(s0 + r) * EMBED + c * 8);
            CP_ASYNC16(smem_u32 + (dsth + FT) * 2,
                       srcK_lo + (size_t)(s0 + r) * EMBED + c * 8);
            CP_ASYNC16(smem_u32 + (dsth + 2 * FT) * 2,
                       srcV_hi + (size_t)r * SEQ + s0 + c * 8);
            CP_ASYNC16(smem_u32 + (dsth + 3 * FT) * 2,
                       srcV_lo + (size_t)r * SEQ + s0 + c * 8);
        }
        asm volatile("cp.async.commit_group;");
    };

    issue(0, 0);

    const int NT = SEQ / 64;
    for (int it = 0; it < NT; it++) {
        if (it + 1 < NT) {
            issue(it + 1, (it + 1) & 1);
            asm volatile("cp.async.wait_group 1;");
        } else {
            asm volatile("cp.async.wait_group 0;");
        }
        __syncthreads();

        const __half* Kh = fsm + (it & 1) * FSTAGE;
        const __half* Kl = Kh + FT;
        const __half* Vh = Kh + 2 * FT;
        const __half* Vl = Kh + 3 * FT;

        float sa[8][4];
#pragma unroll
        for (int nf = 0; nf < 8; nf++)
#pragma unroll
            for (int e = 0; e < 4; e++) sa[nf][e] = 0.f;

#pragma unroll
        for (int s = 0; s < 4; s++) {
            int cc = 16 * s + 2 * tg;
#pragma unroll
            for (int nh = 0; nh < 2; nh++) {
                uint32_t bh[4][2], bl[4][2];
#pragma unroll
                for (int j = 0; j < 4; j++) {
                    int rr = 8 * (4 * nh + j) + g;
                    bh[j][0] = *(const uint32_t*)&Kh[swzh(rr, cc)];
                    bh[j][1] = *(const uint32_t*)&Kh[swzh(rr, cc + 8)];
                    bl[j][0] = *(const uint32_t*)&Kl[swzh(rr, cc)];
                    bl[j][1] = *(const uint32_t*)&Kl[swzh(rr, cc + 8)];
                }
#pragma unroll
                for (int j = 0; j < 4; j++) mma16816(sa[4 * nh + j], qa_h[s], bh[j]);
#pragma unroll
                for (int j = 0; j < 4; j++) mma16816(sa[4 * nh + j], qa_h[s], bl[j]);
#pragma unroll
                for (int j = 0; j < 4; j++) mma16816(sa[4 * nh + j], qa_l[s], bh[j]);
            }
        }

        float mx0 = -1e30f, mx1 = -1e30f;
#pragma unroll
        for (int nf = 0; nf < 8; nf++) {
            mx0 = fmaxf(mx0, fmaxf(sa[nf][0], sa[nf][1]));
            mx1 = fmaxf(mx1, fmaxf(sa[nf][2], sa[nf][3]));
        }
        mx0 = fmaxf(mx0, __shfl_xor_sync(0xffffffffu, mx0, 1));
        mx0 = fmaxf(mx0, __shfl_xor_sync(0xffffffffu, mx0, 2));
        mx1 = fmaxf(mx1, __shfl_xor_sync(0xffffffffu, mx1, 1));
        mx1 = fmaxf(mx1, __shfl_xor_sync(0xffffffffu, mx1, 2));
        float mn0 = fmaxf(m0, mx0), mn1 = fmaxf(m1, mx1);
        float corr0 = __expf(m0 - mn0), corr1 = __expf(m1 - mn1);
        m0 = mn0; m1 = mn1;
        float rs0 = 0.f, rs1 = 0.f;
#pragma unroll
        for (int nf = 0; nf < 8; nf++) {
            sa[nf][0] = __expf(sa[nf][0] - mn0); rs0 += sa[nf][0];
            sa[nf][1] = __expf(sa[nf][1] - mn0); rs0 += sa[nf][1];
            sa[nf][2] = __expf(sa[nf][2] - mn1); rs1 += sa[nf][2];
            sa[nf][3] = __expf(sa[nf][3] - mn1); rs1 += sa[nf][3];
        }
        rs0 += __shfl_xor_sync(0xffffffffu, rs0, 1);
        rs0 += __shfl_xor_sync(0xffffffffu, rs0, 2);
        rs1 += __shfl_xor_sync(0xffffffffu, rs1, 1);
        rs1 += __shfl_xor_sync(0xffffffffu, rs1, 2);
        l0 = l0 * corr0 + rs0;
        l1 = l1 * corr1 + rs1;
#pragma unroll
        for (int nf = 0; nf < 8; nf++) {
            oacc[nf][0] *= corr0; oacc[nf][1] *= corr0;
            oacc[nf][2] *= corr1; oacc[nf][3] *= corr1;
        }

        uint32_t pa_h[4][4], pa_l[4][4];
#pragma unroll
        for (int sp = 0; sp < 4; sp++) {
            pa_h[sp][0] = packf2(sa[2 * sp][0], sa[2 * sp][1]);
            pa_l[sp][0] = packlo(sa[2 * sp][0], sa[2 * sp][1], pa_h[sp][0]);
            pa_h[sp][1] = packf2(sa[2 * sp][2], sa[2 * sp][3]);
            pa_l[sp][1] = packlo(sa[2 * sp][2], sa[2 * sp][3], pa_h[sp][1]);
            pa_h[sp][2] = packf2(sa[2 * sp + 1][0], sa[2 * sp + 1][1]);
            pa_l[sp][2] = packlo(sa[2 * sp + 1][0], sa[2 * sp + 1][1], pa_h[sp][2]);
            pa_h[sp][3] = packf2(sa[2 * sp + 1][2], sa[2 * sp + 1][3]);
            pa_l[sp][3] = packlo(sa[2 * sp + 1][2], sa[2 * sp + 1][3], pa_h[sp][3]);
        }

#pragma unroll
        for (int sp = 0; sp < 4; sp++) {
            int cc = 16 * sp + 2 * tg;
#pragma unroll
            for (int nh = 0; nh < 2; nh++) {
                uint32_t bh[4][2], bl[4][2];
#pragma unroll
                for (int j = 0; j < 4; j++) {
                    int rr = 8 * (4 * nh + j) + g;
                    bh[j][0] = *(const uint32_t*)&Vh[swzh(rr, cc)];
                    bh[j][1] = *(const uint32_t*)&Vh[swzh(rr, cc + 8)];
                    bl[j][0] = *(const uint32_t*)&Vl[swzh(rr, cc)];
                    bl[j][1] = *(const uint32_t*)&Vl[swzh(rr, cc + 8)];
                }
#pragma unroll
                for (int j = 0; j < 4; j++) mma16816(oacc[4 * nh + j], pa_h[sp], bh[j]);
#pragma unroll
                for (int j = 0; j < 4; j++) mma16816(oacc[4 * nh + j], pa_h[sp], bl[j]);
#pragma unroll
                for (int j = 0; j < 4; j++) mma16816(oacc[4 * nh + j], pa_l[sp], bh[j]);
            }
        }
        __syncthreads();
    }

    float* Og = g_ctx + ((size_t)n * SEQ + q0 + wm) * EMBED + h * HDIM;
    float inv0 = 1.0f / l0, inv1 = 1.0f / l1;
#pragma unroll
    for (int nf = 0; nf < 8; nf++) {
        int cc = 8 * nf + 2 * tg;
        *(float2*)(Og + (size_t)g * EMBED + cc) =
            make_float2(oacc[nf][0] * inv0, oacc[nf][1] * inv0);
        *(float2*)(Og + (size_t)(g + 8) * EMBED + cc) =
            make_float2(oacc[nf][2] * inv1, oacc[nf][3] * inv1);
    }
}

// ---------------------------------------------------------------------------
// Launch. Only harness pointers (d_in/d_out) cross the host/device boundary.
// ---------------------------------------------------------------------------
extern "C" void kernel_launch(void* const* d_in, const int* in_sizes, int n_in,
                              void* d_out, int out_size)
{
    const float* values  = (const float*)d_in[0];
    const float* keys    = (const float*)d_in[1];
    const float* queries = (const float*)d_in[2];
    const float* b_v = (const float*)d_in[4];
    const float* b_k = (const float*)d_in[6];
    const float* b_q = (const float*)d_in[8];
    const float* W_v = (const float*)d_in[3];
    const float* W_k = (const float*)d_in[5];
    const float* W_q = (const float*)d_in[7];
    const float* W_o = (const float*)d_in[9];
    const float* b_o = (const float*)d_in[10];
    float* out = (float*)d_out;

    cudaFuncSetAttribute(flash16_kernel,
                         cudaFuncAttributeMaxDynamicSharedMemorySize, FLASH16_SMEM);
    cudaFuncSetAttribute(gemm16_kernel,
                         cudaFuncAttributeMaxDynamicSharedMemorySize, GEMM16_SMEM);

    const int XBLK = (NROWS * EMBED) / (256 * 4);      // 4096
    const int WBLK = (EMBED * EMBED) / (256 * 4);      // 1024
    dim3 ggrid(EMBED / 128, NROWS / 128);              // (8, 32)

    // Q projection
    split_kernel<<<XBLK, 256>>>(queries, 0);
    split_kernel<<<WBLK, 256>>>(W_q, 1);
    gemm16_kernel<<<ggrid, 128, GEMM16_SMEM>>>(b_q, nullptr, 0);
    // K projection
    split_kernel<<<XBLK, 256>>>(keys, 0);
    split_kernel<<<WBLK, 256>>>(W_k, 1);
    gemm16_kernel<<<ggrid, 128, GEMM16_SMEM>>>(b_k, nullptr, 1);
    // V projection
    split_kernel<<<XBLK, 256>>>(values, 0);
    split_kernel<<<WBLK, 256>>>(W_v, 1);
    gemm16_kernel<<<ggrid, 128, GEMM16_SMEM>>>(b_v, nullptr, 2);

    // Attention operand prep + flash
    splitk_kernel<<<XBLK, 256>>>();
    splitvt_kernel<<<dim3(SEQ / 64, HEADS, NBATCH), 256>>>();
    flash16_kernel<<<dim3(SEQ / 64, HEADS, NBATCH), 128, FLASH16_SMEM>>>();

    // Output projection: split g_ctx (src_ext = nullptr) and W_o, write d_out.
    split_kernel<<<XBLK, 256>>>(nullptr, 0);
    split_kernel<<<WBLK, 256>>>(W_o, 1);
    gemm16_kernel<<<ggrid, 128, GEMM16_SMEM>>>(b_o, out, -1);
}

// round 8
// speedup vs baseline: 3.8087x; 1.0587x over previous
#include <cuda_runtime.h>
#include <cuda_fp16.h>
#include <cstdint>

#define EMBED  1024
#define HEADS  16
#define HDIM   64
#define NBATCH 2
#define SEQ    2048
#define NROWS  (NBATCH * SEQ)   // 4096

// Scratch (no allocation allowed).
__device__ float  g_q[NROWS * EMBED];
__device__ float  g_v[NROWS * EMBED];
__device__ __half g_khi[NROWS * EMBED];
__device__ __half g_klo[NROWS * EMBED];
__device__ __half g_vthi[NBATCH * HEADS * HDIM * SEQ];
__device__ __half g_vtlo[NBATCH * HEADS * HDIM * SEQ];
// GEMM operand splits (A also doubles as flash-output split).
__device__ __half g_ahi[NROWS * EMBED];
__device__ __half g_alo[NROWS * EMBED];
__device__ __half g_whi[EMBED * EMBED];
__device__ __half g_wlo[EMBED * EMBED];

#define CP_ASYNC16(dst_u32, src_ptr) \
    asm volatile("cp.async.cg.shared.global [%0], [%1], 16;" :: "r"(dst_u32), "l"(src_ptr))

__device__ __forceinline__ void split2(float x, __half& hi, __half& lo) {
    hi = __float2half_rn(x);
    lo = __float2half_rn(x - __half2float(hi));
}
__device__ __forceinline__ uint32_t h2pack(__half a, __half b) {
    __half2 h = __halves2half2(a, b);
    return *(uint32_t*)&h;
}
__device__ __forceinline__ void mma16816(float* c, const uint32_t* a, const uint32_t* b) {
    asm volatile(
        "mma.sync.aligned.m16n8k16.row.col.f32.f16.f16.f32 "
        "{%0,%1,%2,%3}, {%4,%5,%6,%7}, {%8,%9}, {%0,%1,%2,%3};"
        : "+f"(c[0]), "+f"(c[1]), "+f"(c[2]), "+f"(c[3])
        : "r"(a[0]), "r"(a[1]), "r"(a[2]), "r"(a[3]), "r"(b[0]), "r"(b[1]));
}
__device__ __forceinline__ void ldsm_x4(uint32_t& r0, uint32_t& r1,
                                        uint32_t& r2, uint32_t& r3, uint32_t addr) {
    asm volatile("ldmatrix.sync.aligned.m8n8.x4.shared.b16 {%0,%1,%2,%3}, [%4];"
                 : "=r"(r0), "=r"(r1), "=r"(r2), "=r"(r3) : "r"(addr));
}
__device__ __forceinline__ uint32_t packf2(float x, float y) {
    __half2 h = __floats2half2_rn(x, y);
    return *(uint32_t*)&h;
}
__device__ __forceinline__ uint32_t packlo(float x, float y, uint32_t hi) {
    __half2 h = *(__half2*)&hi;
    return packf2(x - __low2float(h), y - __high2float(h));
}

// ---------------------------------------------------------------------------
// fp32 -> fp16 hi/lo split (device-global dsts selected in device code).
// src_ext == nullptr unused now (kept simple). dst_sel: 0 -> A, 1 -> W.
// ---------------------------------------------------------------------------
__global__ __launch_bounds__(256) void split_kernel(
    const float* __restrict__ src, int dst_sel)
{
    __half* hi = (dst_sel == 0) ? g_ahi : g_whi;
    __half* lo = (dst_sel == 0) ? g_alo : g_wlo;
    size_t i = ((size_t)blockIdx.x * 256 + threadIdx.x) * 4;
    float4 x = *(const float4*)(src + i);
    __half h0, l0, h1, l1, h2, l2, h3, l3;
    split2(x.x, h0, l0); split2(x.y, h1, l1);
    split2(x.z, h2, l2); split2(x.w, h3, l3);
    *(uint2*)(hi + i) = make_uint2(h2pack(h0, h1), h2pack(h2, h3));
    *(uint2*)(lo + i) = make_uint2(h2pack(l0, l1), h2pack(l2, l3));
}

// ---------------------------------------------------------------------------
// fp16-split 3-MMA GEMM (NT). ldmatrix fragment loads.
// dst_sel: 0 -> g_q (fp32), 1 -> g_khi/g_klo (split), 2 -> g_v (fp32),
// else out_ext (fp32).
// ---------------------------------------------------------------------------
#define GARR   (128 * 32)
#define GSTAGE (4 * GARR)
#define GEMM16_SMEM (2 * GSTAGE * 2)  // 65536

__device__ __forceinline__ int gswz(int r, int kc) {
    int sr = r >> 1;
    int c  = ((r & 1) << 5) | kc;
    return sr * 64 + ((((c >> 3) ^ (sr & 7)) << 3) | (c & 7));
}

__global__ __launch_bounds__(128) void gemm16_kernel(
    const float* __restrict__ bias, float* __restrict__ out_ext, int dst_sel)
{
    extern __shared__ __half gsm[];
    const __half* Ahi_g = g_ahi;
    const __half* Alo_g = g_alo;
    const __half* Bhi_g = g_whi;
    const __half* Blo_g = g_wlo;

    const int t    = threadIdx.x;
    const int lane = t & 31;
    const int wid  = t >> 5;
    const int g    = lane >> 2;
    const int tg   = lane & 3;
    const int sub  = lane >> 3;    // ldmatrix matrix index
    const int lr   = lane & 7;     // ldmatrix row within matrix
    const int wm   = (wid & 1) * 64;
    const int wn   = (wid >> 1) * 64;
    const int c0 = blockIdx.x * 128;
    const int r0 = blockIdx.y * 128;

    const uint32_t smem_u32 = (uint32_t)__cvta_generic_to_shared(gsm);

    float acc[4][8][4];
#pragma unroll
    for (int mi = 0; mi < 4; mi++)
#pragma unroll
        for (int ni = 0; ni < 8; ni++)
#pragma unroll
            for (int e = 0; e < 4; e++) acc[mi][ni][e] = 0.f;

    auto issue = [&](int buf, int k0) {
#pragma unroll
        for (int i = 0; i < 4; i++) {
            int gid = t + i * 128;
            int row = gid >> 2;
            int ch  = gid & 3;
            uint32_t dst = smem_u32 + (uint32_t)(buf * GSTAGE + gswz(row, ch * 8)) * 2;
            size_t aoff = (size_t)(r0 + row) * EMBED + k0 + ch * 8;
            size_t boff = (size_t)(c0 + row) * EMBED + k0 + ch * 8;
            CP_ASYNC16(dst,                Ahi_g + aoff);
            CP_ASYNC16(dst + GARR * 2,     Alo_g + aoff);
            CP_ASYNC16(dst + 2 * GARR * 2, Bhi_g + boff);
            CP_ASYNC16(dst + 3 * GARR * 2, Blo_g + boff);
        }
        asm volatile("cp.async.commit_group;");
    };

    issue(0, 0);

    const int NT = EMBED / 32;
    for (int it = 0; it < NT; it++) {
        if (it + 1 < NT) {
            issue((it + 1) & 1, (it + 1) * 32);
            asm volatile("cp.async.wait_group 1;");
        } else {
            asm volatile("cp.async.wait_group 0;");
        }
        __syncthreads();

        const uint32_t base = (uint32_t)((it & 1) * GSTAGE);
        const uint32_t aho = base, alo_ = base + GARR;
        const uint32_t bho = base + 2 * GARR, blo_ = base + 3 * GARR;

#pragma unroll
        for (int ks = 0; ks < 2; ks++) {
            const int kc0 = ks * 16;
            // B fragments: rows = wn + n, chunk = kc0 + (sub&1)*8,
            // matrices (frag fp*2 + sub>>1).
            uint32_t bh[8][2], bl[8][2];
#pragma unroll
            for (int fp = 0; fp < 4; fp++) {
                int row = wn + 8 * (2 * fp + (sub >> 1)) + lr;
                int ch  = kc0 + (sub & 1) * 8;
                uint32_t off = (uint32_t)gswz(row, ch);
                ldsm_x4(bh[2*fp][0], bh[2*fp][1], bh[2*fp+1][0], bh[2*fp+1][1],
                        smem_u32 + (bho + off) * 2);
                ldsm_x4(bl[2*fp][0], bl[2*fp][1], bl[2*fp+1][0], bl[2*fp+1][1],
                        smem_u32 + (blo_ + off) * 2);
            }
#pragma unroll
            for (int mi = 0; mi < 4; mi++) {
                // A fragments: m0 rows+0-7 kc0, m1 rows+8-15 kc0, m2/m3 kc0+8.
                int row = wm + mi * 16 + (sub & 1) * 8 + lr;
                int ch  = kc0 + (sub >> 1) * 8;
                uint32_t off = (uint32_t)gswz(row, ch);
                uint32_t ah[4], al[4];
                ldsm_x4(ah[0], ah[1], ah[2], ah[3], smem_u32 + (aho + off) * 2);
                ldsm_x4(al[0], al[1], al[2], al[3], smem_u32 + (alo_ + off) * 2);
#pragma unroll
                for (int ni = 0; ni < 8; ni++) mma16816(acc[mi][ni], ah, bh[ni]);
#pragma unroll
                for (int ni = 0; ni < 8; ni++) mma16816(acc[mi][ni], ah, bl[ni]);
#pragma unroll
                for (int ni = 0; ni < 8; ni++) mma16816(acc[mi][ni], al, bh[ni]);
            }
        }
        __syncthreads();
    }

    if (dst_sel == 1) {
        // K projection: write split hi/lo directly.
#pragma unroll
        for (int mi = 0; mi < 4; mi++) {
            int r = r0 + wm + mi * 16 + g;
#pragma unroll
            for (int ni = 0; ni < 8; ni++) {
                int cc = c0 + wn + ni * 8 + 2 * tg;
                float bx = bias[cc], by = bias[cc + 1];
                float z0 = acc[mi][ni][0] + bx, z1 = acc[mi][ni][1] + by;
                float z2 = acc[mi][ni][2] + bx, z3 = acc[mi][ni][3] + by;
                __half h0,l0,h1,l1,h2,l2,h3,l3;
                split2(z0,h0,l0); split2(z1,h1,l1);
                split2(z2,h2,l2); split2(z3,h3,l3);
                *(uint32_t*)(g_khi + (size_t)r * EMBED + cc)       = h2pack(h0,h1);
                *(uint32_t*)(g_klo + (size_t)r * EMBED + cc)       = h2pack(l0,l1);
                *(uint32_t*)(g_khi + (size_t)(r+8) * EMBED + cc)   = h2pack(h2,h3);
                *(uint32_t*)(g_klo + (size_t)(r+8) * EMBED + cc)   = h2pack(l2,l3);
            }
        }
    } else {
        float* out = out_ext;
        if (!out) out = (dst_sel == 0) ? g_q : g_v;
#pragma unroll
        for (int mi = 0; mi < 4; mi++) {
            int r = r0 + wm + mi * 16 + g;
#pragma unroll
            for (int ni = 0; ni < 8; ni++) {
                int cc = c0 + wn + ni * 8 + 2 * tg;
                float bx = bias[cc], by = bias[cc + 1];
                *(float2*)(out + (size_t)r * EMBED + cc) =
                    make_float2(acc[mi][ni][0] + bx, acc[mi][ni][1] + by);
                *(float2*)(out + (size_t)(r + 8) * EMBED + cc) =
                    make_float2(acc[mi][ni][2] + bx, acc[mi][ni][3] + by);
            }
        }
    }
}

// ---------------------------------------------------------------------------
// V transpose/split for flash.
// ---------------------------------------------------------------------------
__global__ __launch_bounds__(256) void splitvt_kernel() {
    __shared__ float tile[64][65];
    const int n = blockIdx.z, h = blockIdx.y, s0 = blockIdx.x * 64;
    const int t = threadIdx.x;
#pragma unroll
    for (int i = 0; i < 4; i++) {
        int fi = t + i * 256;
        int r  = fi >> 4;
        int c4 = fi & 15;
        float4 v = *(const float4*)(g_v + ((size_t)n * SEQ + s0 + r) * EMBED + h * HDIM + c4 * 4);
        tile[r][c4 * 4 + 0] = v.x; tile[r][c4 * 4 + 1] = v.y;
        tile[r][c4 * 4 + 2] = v.z; tile[r][c4 * 4 + 3] = v.w;
    }
    __syncthreads();
#pragma unroll
    for (int i = 0; i < 4; i++) {
        int fi = t + i * 256;
        int d   = fi >> 4;
        int sc4 = fi & 15;
        size_t base = ((size_t)(n * HEADS + h) * HDIM + d) * SEQ + s0 + sc4 * 4;
        __half hh[4], ll[4];
#pragma unroll
        for (int j = 0; j < 4; j++) split2(tile[sc4 * 4 + j][d], hh[j], ll[j]);
        *(uint2*)(g_vthi + base) = make_uint2(h2pack(hh[0], hh[1]), h2pack(hh[2], hh[3]));
        *(uint2*)(g_vtlo + base) = make_uint2(h2pack(ll[0], ll[1]), h2pack(ll[2], ll[3]));
    }
}

// ---------------------------------------------------------------------------
// Tensor-core flash attention, fp16-split (3-MMA), ldmatrix fragment loads.
// Epilogue writes O split hi/lo into g_ahi/g_alo (feeds output projection).
// ---------------------------------------------------------------------------
#define FT  4096
#define FSTAGE (4 * FT)
#define FLASH16_SMEM (2 * FSTAGE * 2)   // 65536 B

__device__ __forceinline__ int swzh(int r, int c) {
    return (r << 6) + ((((c >> 3) ^ (r & 7)) << 3) | (c & 7));
}

__global__ __launch_bounds__(128) void flash16_kernel() {
    extern __shared__ __half fsm[];
    const int n  = blockIdx.z;
    const int h  = blockIdx.y;
    const int q0 = blockIdx.x * 64;
    const int t    = threadIdx.x;
    const int lane = t & 31;
    const int wid  = t >> 5;
    const int g    = lane >> 2;
    const int tg   = lane & 3;
    const int sub  = lane >> 3;
    const int lr   = lane & 7;
    const int wm   = wid * 16;

    const uint32_t smem_u32 = (uint32_t)__cvta_generic_to_shared(fsm);

    uint32_t qa_h[4][4], qa_l[4][4];
    {
        const float* Qg = g_q + ((size_t)n * SEQ + q0 + wm) * EMBED + h * HDIM;
#pragma unroll
        for (int s = 0; s < 4; s++) {
            int c0 = 16 * s + 2 * tg;
#pragma unroll
            for (int rr = 0; rr < 2; rr++) {
                int row = g + rr * 8;
                float2 q01 = *(const float2*)(Qg + (size_t)row * EMBED + c0);
                float2 q23 = *(const float2*)(Qg + (size_t)row * EMBED + c0 + 8);
                q01.x *= 0.125f; q01.y *= 0.125f;
                q23.x *= 0.125f; q23.y *= 0.125f;
                qa_h[s][rr]     = packf2(q01.x, q01.y);
                qa_l[s][rr]     = packlo(q01.x, q01.y, qa_h[s][rr]);
                qa_h[s][rr + 2] = packf2(q23.x, q23.y);
                qa_l[s][rr + 2] = packlo(q23.x, q23.y, qa_h[s][rr + 2]);
            }
        }
    }

    float oacc[8][4];
#pragma unroll
    for (int nf = 0; nf < 8; nf++)
#pragma unroll
        for (int e = 0; e < 4; e++) oacc[nf][e] = 0.f;
    float m0 = -1e30f, m1 = -1e30f, l0 = 0.f, l1 = 0.f;

    const __half* srcK_hi = g_khi + ((size_t)n * SEQ) * EMBED + h * HDIM;
    const __half* srcK_lo = g_klo + ((size_t)n * SEQ) * EMBED + h * HDIM;
    const __half* srcV_hi = g_vthi + (size_t)(n * HEADS + h) * HDIM * SEQ;
    const __half* srcV_lo = g_vtlo + (size_t)(n * HEADS + h) * HDIM * SEQ;

    auto issue = [&](int tileidx, int buf) {
        int s0 = tileidx * 64;
#pragma unroll
        for (int i = 0; i < 4; i++) {
            int gid = t + i * 128;
            int r = gid >> 3;
            int c = gid & 7;
            uint32_t dsth = (uint32_t)(buf * FSTAGE + r * 64 + ((c ^ (r & 7)) << 3));
            CP_ASYNC16(smem_u32 + (dsth) * 2,
                       srcK_hi + (size_t)(s0 + r) * EMBED + c * 8);
            CP_ASYNC16(smem_u32 + (dsth + FT) * 2,
                       srcK_lo + (size_t)(s0 + r) * EMBED + c * 8);
            CP_ASYNC16(smem_u32 + (dsth + 2 * FT) * 2,
                       srcV_hi + (size_t)r * SEQ + s0 + c * 8);
            CP_ASYNC16(smem_u32 + (dsth + 3 * FT) * 2,
                       srcV_lo + (size_t)r * SEQ + s0 + c * 8);
        }
        asm volatile("cp.async.commit_group;");
    };

    issue(0, 0);

    const int NT = SEQ / 64;
    for (int it = 0; it < NT; it++) {
        if (it + 1 < NT) {
            issue(it + 1, (it + 1) & 1);
            asm volatile("cp.async.wait_group 1;");
        } else {
            asm volatile("cp.async.wait_group 0;");
        }
        __syncthreads();

        const uint32_t kho = (uint32_t)((it & 1) * FSTAGE);
        const uint32_t klo_ = kho + FT;
        const uint32_t vho = kho + 2 * FT;
        const uint32_t vlo_ = kho + 3 * FT;

        float sa[8][4];
#pragma unroll
        for (int nf = 0; nf < 8; nf++)
#pragma unroll
            for (int e = 0; e < 4; e++) sa[nf][e] = 0.f;

#pragma unroll
        for (int s = 0; s < 4; s++) {
            uint32_t bh[8][2], bl[8][2];
#pragma unroll
            for (int fp = 0; fp < 4; fp++) {
                int row = 8 * (2 * fp + (sub >> 1)) + lr;
                int ch  = 16 * s + (sub & 1) * 8;
                uint32_t off = (uint32_t)swzh(row, ch);
                ldsm_x4(bh[2*fp][0], bh[2*fp][1], bh[2*fp+1][0], bh[2*fp+1][1],
                        smem_u32 + (kho + off) * 2);
                ldsm_x4(bl[2*fp][0], bl[2*fp][1], bl[2*fp+1][0], bl[2*fp+1][1],
                        smem_u32 + (klo_ + off) * 2);
            }
#pragma unroll
            for (int j = 0; j < 8; j++) mma16816(sa[j], qa_h[s], bh[j]);
#pragma unroll
            for (int j = 0; j < 8; j++) mma16816(sa[j], qa_h[s], bl[j]);
#pragma unroll
            for (int j = 0; j < 8; j++) mma16816(sa[j], qa_l[s], bh[j]);
        }

        float mx0 = -1e30f, mx1 = -1e30f;
#pragma unroll
        for (int nf = 0; nf < 8; nf++) {
            mx0 = fmaxf(mx0, fmaxf(sa[nf][0], sa[nf][1]));
            mx1 = fmaxf(mx1, fmaxf(sa[nf][2], sa[nf][3]));
        }
        mx0 = fmaxf(mx0, __shfl_xor_sync(0xffffffffu, mx0, 1));
        mx0 = fmaxf(mx0, __shfl_xor_sync(0xffffffffu, mx0, 2));
        mx1 = fmaxf(mx1, __shfl_xor_sync(0xffffffffu, mx1, 1));
        mx1 = fmaxf(mx1, __shfl_xor_sync(0xffffffffu, mx1, 2));
        float mn0 = fmaxf(m0, mx0), mn1 = fmaxf(m1, mx1);
        float corr0 = __expf(m0 - mn0), corr1 = __expf(m1 - mn1);
        m0 = mn0; m1 = mn1;
        float rs0 = 0.f, rs1 = 0.f;
#pragma unroll
        for (int nf = 0; nf < 8; nf++) {
            sa[nf][0] = __expf(sa[nf][0] - mn0); rs0 += sa[nf][0];
            sa[nf][1] = __expf(sa[nf][1] - mn0); rs0 += sa[nf][1];
            sa[nf][2] = __expf(sa[nf][2] - mn1); rs1 += sa[nf][2];
            sa[nf][3] = __expf(sa[nf][3] - mn1); rs1 += sa[nf][3];
        }
        rs0 += __shfl_xor_sync(0xffffffffu, rs0, 1);
        rs0 += __shfl_xor_sync(0xffffffffu, rs0, 2);
        rs1 += __shfl_xor_sync(0xffffffffu, rs1, 1);
        rs1 += __shfl_xor_sync(0xffffffffu, rs1, 2);
        l0 = l0 * corr0 + rs0;
        l1 = l1 * corr1 + rs1;
#pragma unroll
        for (int nf = 0; nf < 8; nf++) {
            oacc[nf][0] *= corr0; oacc[nf][1] *= corr0;
            oacc[nf][2] *= corr1; oacc[nf][3] *= corr1;
        }

        uint32_t pa_h[4][4], pa_l[4][4];
#pragma unroll
        for (int sp = 0; sp < 4; sp++) {
            pa_h[sp][0] = packf2(sa[2 * sp][0], sa[2 * sp][1]);
            pa_l[sp][0] = packlo(sa[2 * sp][0], sa[2 * sp][1], pa_h[sp][0]);
            pa_h[sp][1] = packf2(sa[2 * sp][2], sa[2 * sp][3]);
            pa_l[sp][1] = packlo(sa[2 * sp][2], sa[2 * sp][3], pa_h[sp][1]);
            pa_h[sp][2] = packf2(sa[2 * sp + 1][0], sa[2 * sp + 1][1]);
            pa_l[sp][2] = packlo(sa[2 * sp + 1][0], sa[2 * sp + 1][1], pa_h[sp][2]);
            pa_h[sp][3] = packf2(sa[2 * sp + 1][2], sa[2 * sp + 1][3]);
            pa_l[sp][3] = packlo(sa[2 * sp + 1][2], sa[2 * sp + 1][3], pa_h[sp][3]);
        }

#pragma unroll
        for (int sp = 0; sp < 4; sp++) {
            uint32_t bh[8][2], bl[8][2];
#pragma unroll
            for (int fp = 0; fp < 4; fp++) {
                int row = 8 * (2 * fp + (sub >> 1)) + lr;    // d rows
                int ch  = 16 * sp + (sub & 1) * 8;           // seq cols
                uint32_t off = (uint32_t)swzh(row, ch);
                ldsm_x4(bh[2*fp][0], bh[2*fp][1], bh[2*fp+1][0], bh[2*fp+1][1],
                        smem_u32 + (vho + off) * 2);
                ldsm_x4(bl[2*fp][0], bl[2*fp][1], bl[2*fp+1][0], bl[2*fp+1][1],
                        smem_u32 + (vlo_ + off) * 2);
            }
#pragma unroll
            for (int j = 0; j < 8; j++) mma16816(oacc[j], pa_h[sp], bh[j]);
#pragma unroll
            for (int j = 0; j < 8; j++) mma16816(oacc[j], pa_h[sp], bl[j]);
#pragma unroll
            for (int j = 0; j < 8; j++) mma16816(oacc[j], pa_l[sp], bh[j]);
        }
        __syncthreads();
    }

    // Epilogue: write O split hi/lo directly into the GEMM A-operand arrays.
    size_t row0 = (size_t)n * SEQ + q0 + wm + g;
    int colb = h * HDIM;
    float inv0 = 1.0f / l0, inv1 = 1.0f / l1;
#pragma unroll
    for (int nf = 0; nf < 8; nf++) {
        int cc = colb + 8 * nf + 2 * tg;
        float z0 = oacc[nf][0] * inv0, z1 = oacc[nf][1] * inv0;
        float z2 = oacc[nf][2] * inv1, z3 = oacc[nf][3] * inv1;
        __half h0,l0h,h1,l1h,h2,l2h,h3,l3h;
        split2(z0,h0,l0h); split2(z1,h1,l1h);
        split2(z2,h2,l2h); split2(z3,h3,l3h);
        *(uint32_t*)(g_ahi + row0 * EMBED + cc)       = h2pack(h0,h1);
        *(uint32_t*)(g_alo + row0 * EMBED + cc)       = h2pack(l0h,l1h);
        *(uint32_t*)(g_ahi + (row0 + 8) * EMBED + cc) = h2pack(h2,h3);
        *(uint32_t*)(g_alo + (row0 + 8) * EMBED + cc) = h2pack(l2h,l3h);
    }
}

// ---------------------------------------------------------------------------
// Launch
// ---------------------------------------------------------------------------
extern "C" void kernel_launch(void* const* d_in, const int* in_sizes, int n_in,
                              void* d_out, int out_size)
{
    const float* values  = (const float*)d_in[0];
    const float* keys    = (const float*)d_in[1];
    const float* queries = (const float*)d_in[2];
    const float* W_v = (const float*)d_in[3];
    const float* b_v = (const float*)d_in[4];
    const float* W_k = (const float*)d_in[5];
    const float* b_k = (const float*)d_in[6];
    const float* W_q = (const float*)d_in[7];
    const float* b_q = (const float*)d_in[8];
    const float* W_o = (const float*)d_in[9];
    const float* b_o = (const float*)d_in[10];
    float* out = (float*)d_out;

    cudaFuncSetAttribute(flash16_kernel,
                         cudaFuncAttributeMaxDynamicSharedMemorySize, FLASH16_SMEM);
    cudaFuncSetAttribute(gemm16_kernel,
                         cudaFuncAttributeMaxDynamicSharedMemorySize, GEMM16_SMEM);

    const int XBLK = (NROWS * EMBED) / (256 * 4);      // 4096
    const int WBLK = (EMBED * EMBED) / (256 * 4);      // 1024
    dim3 ggrid(EMBED / 128, NROWS / 128);              // (8, 32)

    // Q projection -> g_q (fp32)
    split_kernel<<<XBLK, 256>>>(queries, 0);
    split_kernel<<<WBLK, 256>>>(W_q, 1);
    gemm16_kernel<<<ggrid, 128, GEMM16_SMEM>>>(b_q, nullptr, 0);
    // K projection -> g_khi/g_klo (split epilogue)
    split_kernel<<<XBLK, 256>>>(keys, 0);
    split_kernel<<<WBLK, 256>>>(W_k, 1);
    gemm16_kernel<<<ggrid, 128, GEMM16_SMEM>>>(b_k, nullptr, 1);
    // V projection -> g_v (fp32)
    split_kernel<<<XBLK, 256>>>(values, 0);
    split_kernel<<<WBLK, 256>>>(W_v, 1);
    gemm16_kernel<<<ggrid, 128, GEMM16_SMEM>>>(b_v, nullptr, 2);

    // V transpose/split + flash (flash writes g_ahi/g_alo)
    splitvt_kernel<<<dim3(SEQ / 64, HEADS, NBATCH), 256>>>();
    flash16_kernel<<<dim3(SEQ / 64, HEADS, NBATCH), 128, FLASH16_SMEM>>>();

    // Output projection (A already split by flash epilogue)
    split_kernel<<<WBLK, 256>>>(W_o, 1);
    gemm16_kernel<<<ggrid, 128, GEMM16_SMEM>>>(b_o, out, -1);
}

// round 9
// speedup vs baseline: 4.0390x; 1.0605x over previous
#include <cuda_runtime.h>
#include <cuda_fp16.h>
#include <cstdint>

#define EMBED  1024
#define HEADS  16
#define HDIM   64
#define NBATCH 2
#define SEQ    2048
#define NROWS  (NBATCH * SEQ)   // 4096
#define ESQ    (EMBED * EMBED)
#define XSZ    (NROWS * EMBED)

// Scratch (no allocation allowed).
__device__ float  g_q[XSZ];
__device__ float  g_v[XSZ];
__device__ __half g_khi[XSZ];
__device__ __half g_klo[XSZ];
__device__ __half g_vthi[NBATCH * HEADS * HDIM * SEQ];
__device__ __half g_vtlo[NBATCH * HEADS * HDIM * SEQ];
// Input splits: slots 0=values, 1=keys, 2=queries.
__device__ __half g_xhi[3 * XSZ];
__device__ __half g_xlo[3 * XSZ];
// Weight splits: slots 0=W_v, 1=W_k, 2=W_q, 3=W_o.
__device__ __half g_whi[4 * ESQ];
__device__ __half g_wlo[4 * ESQ];
// Flash output split (A operand of the O projection).
__device__ __half g_ahi[XSZ];
__device__ __half g_alo[XSZ];

#define CP_ASYNC16(dst_u32, src_ptr) \
    asm volatile("cp.async.cg.shared.global [%0], [%1], 16;" :: "r"(dst_u32), "l"(src_ptr))

__device__ __forceinline__ void split2(float x, __half& hi, __half& lo) {
    hi = __float2half_rn(x);
    lo = __float2half_rn(x - __half2float(hi));
}
__device__ __forceinline__ uint32_t h2pack(__half a, __half b) {
    __half2 h = __halves2half2(a, b);
    return *(uint32_t*)&h;
}
__device__ __forceinline__ void mma16816(float* c, const uint32_t* a, const uint32_t* b) {
    asm volatile(
        "mma.sync.aligned.m16n8k16.row.col.f32.f16.f16.f32 "
        "{%0,%1,%2,%3}, {%4,%5,%6,%7}, {%8,%9}, {%0,%1,%2,%3};"
        : "+f"(c[0]), "+f"(c[1]), "+f"(c[2]), "+f"(c[3])
        : "r"(a[0]), "r"(a[1]), "r"(a[2]), "r"(a[3]), "r"(b[0]), "r"(b[1]));
}
__device__ __forceinline__ void ldsm_x4(uint32_t& r0, uint32_t& r1,
                                        uint32_t& r2, uint32_t& r3, uint32_t addr) {
    asm volatile("ldmatrix.sync.aligned.m8n8.x4.shared.b16 {%0,%1,%2,%3}, [%4];"
                 : "=r"(r0), "=r"(r1), "=r"(r2), "=r"(r3) : "r"(addr));
}
__device__ __forceinline__ uint32_t packf2(float x, float y) {
    __half2 h = __floats2half2_rn(x, y);
    return *(uint32_t*)&h;
}
__device__ __forceinline__ uint32_t packlo(float x, float y, uint32_t hi) {
    __half2 h = *(__half2*)&hi;
    return packf2(x - __low2float(h), y - __high2float(h));
}

// ---------------------------------------------------------------------------
// Batched splits. Destinations picked in device code (device-global symbols
// must never cross the host boundary).
// ---------------------------------------------------------------------------
__global__ __launch_bounds__(256) void splitx_kernel(
    const float* __restrict__ values, const float* __restrict__ keys,
    const float* __restrict__ queries)
{
    const int slot = blockIdx.y;
    const float* src = (slot == 0) ? values : (slot == 1) ? keys : queries;
    __half* hi = g_xhi + (size_t)slot * XSZ;
    __half* lo = g_xlo + (size_t)slot * XSZ;
    size_t i = ((size_t)blockIdx.x * 256 + threadIdx.x) * 4;
    float4 x = *(const float4*)(src + i);
    __half h0, l0, h1, l1, h2, l2, h3, l3;
    split2(x.x, h0, l0); split2(x.y, h1, l1);
    split2(x.z, h2, l2); split2(x.w, h3, l3);
    *(uint2*)(hi + i) = make_uint2(h2pack(h0, h1), h2pack(h2, h3));
    *(uint2*)(lo + i) = make_uint2(h2pack(l0, l1), h2pack(l2, l3));
}

__global__ __launch_bounds__(256) void splitw_kernel(
    const float* __restrict__ Wv, const float* __restrict__ Wk,
    const float* __restrict__ Wq, const float* __restrict__ Wo)
{
    const int slot = blockIdx.y;
    const float* src = (slot == 0) ? Wv : (slot == 1) ? Wk : (slot == 2) ? Wq : Wo;
    __half* hi = g_whi + (size_t)slot * ESQ;
    __half* lo = g_wlo + (size_t)slot * ESQ;
    size_t i = ((size_t)blockIdx.x * 256 + threadIdx.x) * 4;
    float4 x = *(const float4*)(src + i);
    __half h0, l0, h1, l1, h2, l2, h3, l3;
    split2(x.x, h0, l0); split2(x.y, h1, l1);
    split2(x.z, h2, l2); split2(x.w, h3, l3);
    *(uint2*)(hi + i) = make_uint2(h2pack(h0, h1), h2pack(h2, h3));
    *(uint2*)(lo + i) = make_uint2(h2pack(l0, l1), h2pack(l2, l3));
}

// ---------------------------------------------------------------------------
// fp16-split 3-MMA GEMM (NT). mode 0: fused QKV (z = blockIdx.z picks
// operands/dst); mode 1: O projection (A = flash output split, out = out_ext).
// ---------------------------------------------------------------------------
#define GARR   (128 * 32)
#define GSTAGE (4 * GARR)
#define GEMM16_SMEM (2 * GSTAGE * 2)  // 65536

__device__ __forceinline__ int gswz(int r, int kc) {
    int sr = r >> 1;
    int c  = ((r & 1) << 5) | kc;
    return sr * 64 + ((((c >> 3) ^ (sr & 7)) << 3) | (c & 7));
}

__global__ __launch_bounds__(128) void gemm16_kernel(
    const float* __restrict__ bq, const float* __restrict__ bk,
    const float* __restrict__ bv, float* __restrict__ out_ext, int mode)
{
    extern __shared__ __half gsm[];
    const int z = (mode == 0) ? (int)blockIdx.z : 3;   // 0=Q 1=K 2=V 3=O
    const int wslot = (z == 0) ? 2 : (z == 1) ? 1 : (z == 2) ? 0 : 3;

    const __half *Ahi_g, *Alo_g;
    const float* bias;
    if (z < 3) {
        const int xslot = (z == 0) ? 2 : (z == 1) ? 1 : 0;
        Ahi_g = g_xhi + (size_t)xslot * XSZ;
        Alo_g = g_xlo + (size_t)xslot * XSZ;
        bias  = (z == 0) ? bq : (z == 1) ? bk : bv;
    } else {
        Ahi_g = g_ahi;
        Alo_g = g_alo;
        bias  = bq;              // O launch passes b_o here
    }
    const __half* Bhi_g = g_whi + (size_t)wslot * ESQ;
    const __half* Blo_g = g_wlo + (size_t)wslot * ESQ;

    const int t    = threadIdx.x;
    const int lane = t & 31;
    const int wid  = t >> 5;
    const int g    = lane >> 2;
    const int tg   = lane & 3;
    const int sub  = lane >> 3;
    const int lr   = lane & 7;
    const int wm   = (wid & 1) * 64;
    const int wn   = (wid >> 1) * 64;
    const int c0 = blockIdx.x * 128;
    const int r0 = blockIdx.y * 128;

    const uint32_t smem_u32 = (uint32_t)__cvta_generic_to_shared(gsm);

    float acc[4][8][4];
#pragma unroll
    for (int mi = 0; mi < 4; mi++)
#pragma unroll
        for (int ni = 0; ni < 8; ni++)
#pragma unroll
            for (int e = 0; e < 4; e++) acc[mi][ni][e] = 0.f;

    auto issue = [&](int buf, int k0) {
#pragma unroll
        for (int i = 0; i < 4; i++) {
            int gid = t + i * 128;
            int row = gid >> 2;
            int ch  = gid & 3;
            uint32_t dst = smem_u32 + (uint32_t)(buf * GSTAGE + gswz(row, ch * 8)) * 2;
            size_t aoff = (size_t)(r0 + row) * EMBED + k0 + ch * 8;
            size_t boff = (size_t)(c0 + row) * EMBED + k0 + ch * 8;
            CP_ASYNC16(dst,                Ahi_g + aoff);
            CP_ASYNC16(dst + GARR * 2,     Alo_g + aoff);
            CP_ASYNC16(dst + 2 * GARR * 2, Bhi_g + boff);
            CP_ASYNC16(dst + 3 * GARR * 2, Blo_g + boff);
        }
        asm volatile("cp.async.commit_group;");
    };

    issue(0, 0);

    const int NT = EMBED / 32;
    for (int it = 0; it < NT; it++) {
        if (it + 1 < NT) {
            issue((it + 1) & 1, (it + 1) * 32);
            asm volatile("cp.async.wait_group 1;");
        } else {
            asm volatile("cp.async.wait_group 0;");
        }
        __syncthreads();

        const uint32_t base = (uint32_t)((it & 1) * GSTAGE);
        const uint32_t aho = base, alo_ = base + GARR;
        const uint32_t bho = base + 2 * GARR, blo_ = base + 3 * GARR;

#pragma unroll
        for (int ks = 0; ks < 2; ks++) {
            const int kc0 = ks * 16;
            uint32_t bh[8][2], bl[8][2];
#pragma unroll
            for (int fp = 0; fp < 4; fp++) {
                int row = wn + 8 * (2 * fp + (sub >> 1)) + lr;
                int ch  = kc0 + (sub & 1) * 8;
                uint32_t off = (uint32_t)gswz(row, ch);
                ldsm_x4(bh[2*fp][0], bh[2*fp][1], bh[2*fp+1][0], bh[2*fp+1][1],
                        smem_u32 + (bho + off) * 2);
                ldsm_x4(bl[2*fp][0], bl[2*fp][1], bl[2*fp+1][0], bl[2*fp+1][1],
                        smem_u32 + (blo_ + off) * 2);
            }
#pragma unroll
            for (int mi = 0; mi < 4; mi++) {
                int row = wm + mi * 16 + (sub & 1) * 8 + lr;
                int ch  = kc0 + (sub >> 1) * 8;
                uint32_t off = (uint32_t)gswz(row, ch);
                uint32_t ah[4], al[4];
                ldsm_x4(ah[0], ah[1], ah[2], ah[3], smem_u32 + (aho + off) * 2);
                ldsm_x4(al[0], al[1], al[2], al[3], smem_u32 + (alo_ + off) * 2);
#pragma unroll
                for (int ni = 0; ni < 8; ni++) mma16816(acc[mi][ni], ah, bh[ni]);
#pragma unroll
                for (int ni = 0; ni < 8; ni++) mma16816(acc[mi][ni], ah, bl[ni]);
#pragma unroll
                for (int ni = 0; ni < 8; ni++) mma16816(acc[mi][ni], al, bh[ni]);
            }
        }
        __syncthreads();
    }

    if (z == 1) {
        // K projection: write split hi/lo directly.
#pragma unroll
        for (int mi = 0; mi < 4; mi++) {
            int r = r0 + wm + mi * 16 + g;
#pragma unroll
            for (int ni = 0; ni < 8; ni++) {
                int cc = c0 + wn + ni * 8 + 2 * tg;
                float bx = bias[cc], by = bias[cc + 1];
                float z0 = acc[mi][ni][0] + bx, z1 = acc[mi][ni][1] + by;
                float z2 = acc[mi][ni][2] + bx, z3 = acc[mi][ni][3] + by;
                __half h0,l0,h1,l1,h2,l2,h3,l3;
                split2(z0,h0,l0); split2(z1,h1,l1);
                split2(z2,h2,l2); split2(z3,h3,l3);
                *(uint32_t*)(g_khi + (size_t)r * EMBED + cc)     = h2pack(h0,h1);
                *(uint32_t*)(g_klo + (size_t)r * EMBED + cc)     = h2pack(l0,l1);
                *(uint32_t*)(g_khi + (size_t)(r+8) * EMBED + cc) = h2pack(h2,h3);
                *(uint32_t*)(g_klo + (size_t)(r+8) * EMBED + cc) = h2pack(l2,l3);
            }
        }
    } else {
        float* out = (z == 0) ? g_q : (z == 2) ? g_v : out_ext;
#pragma unroll
        for (int mi = 0; mi < 4; mi++) {
            int r = r0 + wm + mi * 16 + g;
#pragma unroll
            for (int ni = 0; ni < 8; ni++) {
                int cc = c0 + wn + ni * 8 + 2 * tg;
                float bx = bias[cc], by = bias[cc + 1];
                *(float2*)(out + (size_t)r * EMBED + cc) =
                    make_float2(acc[mi][ni][0] + bx, acc[mi][ni][1] + by);
                *(float2*)(out + (size_t)(r + 8) * EMBED + cc) =
                    make_float2(acc[mi][ni][2] + bx, acc[mi][ni][3] + by);
            }
        }
    }
}

// ---------------------------------------------------------------------------
// V transpose/split for flash.
// ---------------------------------------------------------------------------
__global__ __launch_bounds__(256) void splitvt_kernel() {
    __shared__ float tile[64][65];
    const int n = blockIdx.z, h = blockIdx.y, s0 = blockIdx.x * 64;
    const int t = threadIdx.x;
#pragma unroll
    for (int i = 0; i < 4; i++) {
        int fi = t + i * 256;
        int r  = fi >> 4;
        int c4 = fi & 15;
        float4 v = *(const float4*)(g_v + ((size_t)n * SEQ + s0 + r) * EMBED + h * HDIM + c4 * 4);
        tile[r][c4 * 4 + 0] = v.x; tile[r][c4 * 4 + 1] = v.y;
        tile[r][c4 * 4 + 2] = v.z; tile[r][c4 * 4 + 3] = v.w;
    }
    __syncthreads();
#pragma unroll
    for (int i = 0; i < 4; i++) {
        int fi = t + i * 256;
        int d   = fi >> 4;
        int sc4 = fi & 15;
        size_t base = ((size_t)(n * HEADS + h) * HDIM + d) * SEQ + s0 + sc4 * 4;
        __half hh[4], ll[4];
#pragma unroll
        for (int j = 0; j < 4; j++) split2(tile[sc4 * 4 + j][d], hh[j], ll[j]);
        *(uint2*)(g_vthi + base) = make_uint2(h2pack(hh[0], hh[1]), h2pack(hh[2], hh[3]));
        *(uint2*)(g_vtlo + base) = make_uint2(h2pack(ll[0], ll[1]), h2pack(ll[2], ll[3]));
    }
}

// ---------------------------------------------------------------------------
// Tensor-core flash attention, fp16-split (3-MMA), ldmatrix loads (proven R8).
// ---------------------------------------------------------------------------
#define FT  4096
#define FSTAGE (4 * FT)
#define FLASH16_SMEM (2 * FSTAGE * 2)   // 65536 B

__device__ __forceinline__ int swzh(int r, int c) {
    return (r << 6) + ((((c >> 3) ^ (r & 7)) << 3) | (c & 7));
}

__global__ __launch_bounds__(128) void flash16_kernel() {
    extern __shared__ __half fsm[];
    const int n  = blockIdx.z;
    const int h  = blockIdx.y;
    const int q0 = blockIdx.x * 64;
    const int t    = threadIdx.x;
    const int lane = t & 31;
    const int wid  = t >> 5;
    const int g    = lane >> 2;
    const int tg   = lane & 3;
    const int sub  = lane >> 3;
    const int lr   = lane & 7;
    const int wm   = wid * 16;

    const uint32_t smem_u32 = (uint32_t)__cvta_generic_to_shared(fsm);

    uint32_t qa_h[4][4], qa_l[4][4];
    {
        const float* Qg = g_q + ((size_t)n * SEQ + q0 + wm) * EMBED + h * HDIM;
#pragma unroll
        for (int s = 0; s < 4; s++) {
            int c0 = 16 * s + 2 * tg;
#pragma unroll
            for (int rr = 0; rr < 2; rr++) {
                int row = g + rr * 8;
                float2 q01 = *(const float2*)(Qg + (size_t)row * EMBED + c0);
                float2 q23 = *(const float2*)(Qg + (size_t)row * EMBED + c0 + 8);
                q01.x *= 0.125f; q01.y *= 0.125f;
                q23.x *= 0.125f; q23.y *= 0.125f;
                qa_h[s][rr]     = packf2(q01.x, q01.y);
                qa_l[s][rr]     = packlo(q01.x, q01.y, qa_h[s][rr]);
                qa_h[s][rr + 2] = packf2(q23.x, q23.y);
                qa_l[s][rr + 2] = packlo(q23.x, q23.y, qa_h[s][rr + 2]);
            }
        }
    }

    float oacc[8][4];
#pragma unroll
    for (int nf = 0; nf < 8; nf++)
#pragma unroll
        for (int e = 0; e < 4; e++) oacc[nf][e] = 0.f;
    float m0 = -1e30f, m1 = -1e30f, l0 = 0.f, l1 = 0.f;

    const __half* srcK_hi = g_khi + ((size_t)n * SEQ) * EMBED + h * HDIM;
    const __half* srcK_lo = g_klo + ((size_t)n * SEQ) * EMBED + h * HDIM;
    const __half* srcV_hi = g_vthi + (size_t)(n * HEADS + h) * HDIM * SEQ;
    const __half* srcV_lo = g_vtlo + (size_t)(n * HEADS + h) * HDIM * SEQ;

    auto issue = [&](int tileidx, int buf) {
        int s0 = tileidx * 64;
#pragma unroll
        for (int i = 0; i < 4; i++) {
            int gid = t + i * 128;
            int r = gid >> 3;
            int c = gid & 7;
            uint32_t dsth = (uint32_t)(buf * FSTAGE + r * 64 + ((c ^ (r & 7)) << 3));
            CP_ASYNC16(smem_u32 + (dsth) * 2,
                       srcK_hi + (size_t)(s0 + r) * EMBED + c * 8);
            CP_ASYNC16(smem_u32 + (dsth + FT) * 2,
                       srcK_lo + (size_t)(s0 + r) * EMBED + c * 8);
            CP_ASYNC16(smem_u32 + (dsth + 2 * FT) * 2,
                       srcV_hi + (size_t)r * SEQ + s0 + c * 8);
            CP_ASYNC16(smem_u32 + (dsth + 3 * FT) * 2,
                       srcV_lo + (size_t)r * SEQ + s0 + c * 8);
        }
        asm volatile("cp.async.commit_group;");
    };

    issue(0, 0);

    const int NT = SEQ / 64;
    for (int it = 0; it < NT; it++) {
        if (it + 1 < NT) {
            issue(it + 1, (it + 1) & 1);
            asm volatile("cp.async.wait_group 1;");
        } else {
            asm volatile("cp.async.wait_group 0;");
        }
        __syncthreads();

        const uint32_t kho = (uint32_t)((it & 1) * FSTAGE);
        const uint32_t klo_ = kho + FT;
        const uint32_t vho = kho + 2 * FT;
        const uint32_t vlo_ = kho + 3 * FT;

        float sa[8][4];
#pragma unroll
        for (int nf = 0; nf < 8; nf++)
#pragma unroll
            for (int e = 0; e < 4; e++) sa[nf][e] = 0.f;

#pragma unroll
        for (int s = 0; s < 4; s++) {
            uint32_t bh[8][2], bl[8][2];
#pragma unroll
            for (int fp = 0; fp < 4; fp++) {
                int row = 8 * (2 * fp + (sub >> 1)) + lr;
                int ch  = 16 * s + (sub & 1) * 8;
                uint32_t off = (uint32_t)swzh(row, ch);
                ldsm_x4(bh[2*fp][0], bh[2*fp][1], bh[2*fp+1][0], bh[2*fp+1][1],
                        smem_u32 + (kho + off) * 2);
                ldsm_x4(bl[2*fp][0], bl[2*fp][1], bl[2*fp+1][0], bl[2*fp+1][1],
                        smem_u32 + (klo_ + off) * 2);
            }
#pragma unroll
            for (int j = 0; j < 8; j++) mma16816(sa[j], qa_h[s], bh[j]);
#pragma unroll
            for (int j = 0; j < 8; j++) mma16816(sa[j], qa_h[s], bl[j]);
#pragma unroll
            for (int j = 0; j < 8; j++) mma16816(sa[j], qa_l[s], bh[j]);
        }

        float mx0 = -1e30f, mx1 = -1e30f;
#pragma unroll
        for (int nf = 0; nf < 8; nf++) {
            mx0 = fmaxf(mx0, fmaxf(sa[nf][0], sa[nf][1]));
            mx1 = fmaxf(mx1, fmaxf(sa[nf][2], sa[nf][3]));
        }
        mx0 = fmaxf(mx0, __shfl_xor_sync(0xffffffffu, mx0, 1));
        mx0 = fmaxf(mx0, __shfl_xor_sync(0xffffffffu, mx0, 2));
        mx1 = fmaxf(mx1, __shfl_xor_sync(0xffffffffu, mx1, 1));
        mx1 = fmaxf(mx1, __shfl_xor_sync(0xffffffffu, mx1, 2));
        float mn0 = fmaxf(m0, mx0), mn1 = fmaxf(m1, mx1);
        float corr0 = __expf(m0 - mn0), corr1 = __expf(m1 - mn1);
        m0 = mn0; m1 = mn1;
        float rs0 = 0.f, rs1 = 0.f;
#pragma unroll
        for (int nf = 0; nf < 8; nf++) {
            sa[nf][0] = __expf(sa[nf][0] - mn0); rs0 += sa[nf][0];
            sa[nf][1] = __expf(sa[nf][1] - mn0); rs0 += sa[nf][1];
            sa[nf][2] = __expf(sa[nf][2] - mn1); rs1 += sa[nf][2];
            sa[nf][3] = __expf(sa[nf][3] - mn1); rs1 += sa[nf][3];
        }
        rs0 += __shfl_xor_sync(0xffffffffu, rs0, 1);
        rs0 += __shfl_xor_sync(0xffffffffu, rs0, 2);
        rs1 += __shfl_xor_sync(0xffffffffu, rs1, 1);
        rs1 += __shfl_xor_sync(0xffffffffu, rs1, 2);
        l0 = l0 * corr0 + rs0;
        l1 = l1 * corr1 + rs1;
#pragma unroll
        for (int nf = 0; nf < 8; nf++) {
            oacc[nf][0] *= corr0; oacc[nf][1] *= corr0;
            oacc[nf][2] *= corr1; oacc[nf][3] *= corr1;
        }

        uint32_t pa_h[4][4], pa_l[4][4];
#pragma unroll
        for (int sp = 0; sp < 4; sp++) {
            pa_h[sp][0] = packf2(sa[2 * sp][0], sa[2 * sp][1]);
            pa_l[sp][0] = packlo(sa[2 * sp][0], sa[2 * sp][1], pa_h[sp][0]);
            pa_h[sp][1] = packf2(sa[2 * sp][2], sa[2 * sp][3]);
            pa_l[sp][1] = packlo(sa[2 * sp][2], sa[2 * sp][3], pa_h[sp][1]);
            pa_h[sp][2] = packf2(sa[2 * sp + 1][0], sa[2 * sp + 1][1]);
            pa_l[sp][2] = packlo(sa[2 * sp + 1][0], sa[2 * sp + 1][1], pa_h[sp][2]);
            pa_h[sp][3] = packf2(sa[2 * sp + 1][2], sa[2 * sp + 1][3]);
            pa_l[sp][3] = packlo(sa[2 * sp + 1][2], sa[2 * sp + 1][3], pa_h[sp][3]);
        }

#pragma unroll
        for (int sp = 0; sp < 4; sp++) {
            uint32_t bh[8][2], bl[8][2];
#pragma unroll
            for (int fp = 0; fp < 4; fp++) {
                int row = 8 * (2 * fp + (sub >> 1)) + lr;
                int ch  = 16 * sp + (sub & 1) * 8;
                uint32_t off = (uint32_t)swzh(row, ch);
                ldsm_x4(bh[2*fp][0], bh[2*fp][1], bh[2*fp+1][0], bh[2*fp+1][1],
                        smem_u32 + (vho + off) * 2);
                ldsm_x4(bl[2*fp][0], bl[2*fp][1], bl[2*fp+1][0], bl[2*fp+1][1],
                        smem_u32 + (vlo_ + off) * 2);
            }
#pragma unroll
            for (int j = 0; j < 8; j++) mma16816(oacc[j], pa_h[sp], bh[j]);
#pragma unroll
            for (int j = 0; j < 8; j++) mma16816(oacc[j], pa_h[sp], bl[j]);
#pragma unroll
            for (int j = 0; j < 8; j++) mma16816(oacc[j], pa_l[sp], bh[j]);
        }
        __syncthreads();
    }

    // Epilogue: write O split hi/lo into the O-projection A operand.
    size_t row0 = (size_t)n * SEQ + q0 + wm + g;
    int colb = h * HDIM;
    float inv0 = 1.0f / l0, inv1 = 1.0f / l1;
#pragma unroll
    for (int nf = 0; nf < 8; nf++) {
        int cc = colb + 8 * nf + 2 * tg;
        float z0 = oacc[nf][0] * inv0, z1 = oacc[nf][1] * inv0;
        float z2 = oacc[nf][2] * inv1, z3 = oacc[nf][3] * inv1;
        __half h0,l0h,h1,l1h,h2,l2h,h3,l3h;
        split2(z0,h0,l0h); split2(z1,h1,l1h);
        split2(z2,h2,l2h); split2(z3,h3,l3h);
        *(uint32_t*)(g_ahi + row0 * EMBED + cc)       = h2pack(h0,h1);
        *(uint32_t*)(g_alo + row0 * EMBED + cc)       = h2pack(l0h,l1h);
        *(uint32_t*)(g_ahi + (row0 + 8) * EMBED + cc) = h2pack(h2,h3);
        *(uint32_t*)(g_alo + (row0 + 8) * EMBED + cc) = h2pack(l2h,l3h);
    }
}

// ---------------------------------------------------------------------------
// Launch
// ---------------------------------------------------------------------------
extern "C" void kernel_launch(void* const* d_in, const int* in_sizes, int n_in,
                              void* d_out, int out_size)
{
    const float* values  = (const float*)d_in[0];
    const float* keys    = (const float*)d_in[1];
    const float* queries = (const float*)d_in[2];
    const float* W_v = (const float*)d_in[3];
    const float* b_v = (const float*)d_in[4];
    const float* W_k = (const float*)d_in[5];
    const float* b_k = (const float*)d_in[6];
    const float* W_q = (const float*)d_in[7];
    const float* b_q = (const float*)d_in[8];
    const float* W_o = (const float*)d_in[9];
    const float* b_o = (const float*)d_in[10];
    float* out = (float*)d_out;

    cudaFuncSetAttribute(flash16_kernel,
                         cudaFuncAttributeMaxDynamicSharedMemorySize, FLASH16_SMEM);
    cudaFuncSetAttribute(gemm16_kernel,
                         cudaFuncAttributeMaxDynamicSharedMemorySize, GEMM16_SMEM);

    const int XBLK = XSZ / (256 * 4);                  // 4096
    const int WBLK = ESQ / (256 * 4);                  // 1024

    // Batched operand splits (all weights + all inputs).
    splitw_kernel<<<dim3(WBLK, 4), 256>>>(W_v, W_k, W_q, W_o);
    splitx_kernel<<<dim3(XBLK, 3), 256>>>(values, keys, queries);

    // Fused Q/K/V projections (768 CTAs -> full-chip residency).
    gemm16_kernel<<<dim3(EMBED / 128, NROWS / 128, 3), 128, GEMM16_SMEM>>>(
        b_q, b_k, b_v, nullptr, 0);

    // V transpose/split + flash (flash writes g_ahi/g_alo).
    splitvt_kernel<<<dim3(SEQ / 64, HEADS, NBATCH), 256>>>();
    flash16_kernel<<<dim3(SEQ / 64, HEADS, NBATCH), 128, FLASH16_SMEM>>>();

    // Output projection.
    gemm16_kernel<<<dim3(EMBED / 128, NROWS / 128, 1), 128, GEMM16_SMEM>>>(
        b_o, nullptr, nullptr, out, 1);
}